// round 1
// baseline (speedup 1.0000x reference)
#include <cuda_runtime.h>

// Problem constants (fixed shapes)
static constexpr int Bsz = 32;
static constexpr int C   = 256;
static constexpr int Nn  = 4096;   // H*W = 64*64
static constexpr int S   = 64;
static constexpr int CD  = 128;    // conv_dim = 2*S
static constexpr float EPS = 1e-5f;

// ---------------- scratch (device globals; no runtime allocation) ----------------
__device__ float g_mean[Bsz * Nn];
__device__ float g_inv [Bsz * Nn];
__device__ float g_wp  [CD * C];
__device__ float g_rowsum[CD];
__device__ float g_bias  [CD];
__device__ float g_bcdt[(size_t)Bsz * CD * Nn];   // 64 MB: pre-conv
__device__ float g_cv  [(size_t)Bsz * CD * Nn];   // 64 MB: post-conv (BC rows 0..63, dt rows 64..127)
__device__ float g_AB  [(size_t)Bsz * S  * Nn];   // 32 MB
__device__ float g_hpart[8][(size_t)Bsz * C * S]; // 16 MB: split-K partials (deterministic)
__device__ float g_h   [(size_t)Bsz * C * S];     // 2 MB
__device__ float g_h2  [(size_t)Bsz * C * S];     // 2 MB

// ---------------- K0: fold ln_w/ln_b into projection weights ----------------
// wp[o,c] = w_bcdt[o,c]*ln_w[c]; rowsum[o] = sum_c wp; bias[o] = sum_c w_bcdt[o,c]*ln_b[c]
__global__ void prep_w_k(const float* __restrict__ w_bcdt,
                         const float* __restrict__ ln_w,
                         const float* __restrict__ ln_b) {
    int o = blockIdx.x;        // 128
    int c = threadIdx.x;       // 256
    float w  = w_bcdt[o * C + c];
    float wp = w * ln_w[c];
    g_wp[o * C + c] = wp;
    __shared__ float s1[256], s2[256];
    s1[c] = wp;
    s2[c] = w * ln_b[c];
    __syncthreads();
    for (int st = 128; st > 0; st >>= 1) {
        if (c < st) { s1[c] += s1[c + st]; s2[c] += s2[c + st]; }
        __syncthreads();
    }
    if (c == 0) { g_rowsum[o] = s1[0]; g_bias[o] = s2[0]; }
}

// ---------------- K1: per-(b,n) channel stats ----------------
__global__ void stats_k(const float* __restrict__ x) {
    int idx = blockIdx.x * 256 + threadIdx.x;   // over B*N
    int b = idx >> 12, n = idx & 4095;
    const float* xp = x + (size_t)b * C * Nn + n;
    float s = 0.f, sq = 0.f;
#pragma unroll 8
    for (int c = 0; c < C; c++) {
        float v = xp[(size_t)c * Nn];
        s += v; sq = fmaf(v, v, sq);
    }
    float m   = s * (1.f / 256.f);
    float var = (sq - 256.f * m * m) * (1.f / 255.f);   // unbiased
    g_mean[idx] = m;
    g_inv[idx]  = rsqrtf(var + EPS);
}

// ---------------- K2: GEMM1 (128x4096x256 per batch) with LN epilogue ----------------
__global__ __launch_bounds__(256) void gemm1_k(const float* __restrict__ x) {
    __shared__ float As[8][128];
    __shared__ float Bs[8][132];
    int b  = blockIdx.y;
    int n0 = blockIdx.x * 128;
    const float* Bp = x + (size_t)b * C * Nn;
    int tid = threadIdx.x;
    int tx = tid & 15, ty = tid >> 4;
    float acc[8][8];
#pragma unroll
    for (int i = 0; i < 8; i++)
#pragma unroll
        for (int j = 0; j < 8; j++) acc[i][j] = 0.f;
    int am = tid >> 1, ak = (tid & 1) * 4;
    int bk = tid >> 5, bn = (tid & 31) * 4;
    for (int k0 = 0; k0 < C; k0 += 8) {
        float4 av = *(const float4*)(g_wp + am * C + k0 + ak);
        float4 bv = *(const float4*)(Bp + (size_t)(k0 + bk) * Nn + n0 + bn);
        __syncthreads();
        As[ak + 0][am] = av.x; As[ak + 1][am] = av.y;
        As[ak + 2][am] = av.z; As[ak + 3][am] = av.w;
        Bs[bk][bn + 0] = bv.x; Bs[bk][bn + 1] = bv.y;
        Bs[bk][bn + 2] = bv.z; Bs[bk][bn + 3] = bv.w;
        __syncthreads();
#pragma unroll
        for (int k = 0; k < 8; k++) {
            float a[8], bb[8];
#pragma unroll
            for (int i = 0; i < 8; i++) a[i] = As[k][ty * 8 + i];
#pragma unroll
            for (int j = 0; j < 8; j++) bb[j] = Bs[k][tx * 8 + j];
#pragma unroll
            for (int i = 0; i < 8; i++)
#pragma unroll
                for (int j = 0; j < 8; j++) acc[i][j] = fmaf(a[i], bb[j], acc[i][j]);
        }
    }
    float* outp = g_bcdt + (size_t)b * CD * Nn;
    const float* meanp = g_mean + b * Nn;
    const float* invp  = g_inv  + b * Nn;
#pragma unroll
    for (int i = 0; i < 8; i++) {
        int m = ty * 8 + i;
        float rs = g_rowsum[m], bi = g_bias[m];
#pragma unroll
        for (int j = 0; j < 8; j++) {
            int n = n0 + tx * 8 + j;
            outp[(size_t)m * Nn + n] = invp[n] * (acc[i][j] - meanp[n] * rs) + bi;
        }
    }
}

// ---------------- K3: grouped 3x3 conv (32 groups of 4ch), pad 1 ----------------
__global__ __launch_bounds__(256) void conv_k(const float* __restrict__ w_gw) {
    __shared__ float sin_[4][18][18];
    __shared__ float sw[4][4][9];
    int b = blockIdx.z, g = blockIdx.y, tile = blockIdx.x;
    int tid = threadIdx.x;
    if (tid < 144) {
        int o = tid / 36, r = tid % 36;
        sw[o][r / 9][r % 9] = w_gw[(g * 4 + o) * 36 + r];
    }
    const float* inp = g_bcdt + ((size_t)b * CD + g * 4) * Nn;
    int y0 = (tile >> 2) * 16 - 1, x0 = (tile & 3) * 16 - 1;
    for (int i = tid; i < 4 * 324; i += 256) {
        int ch = i / 324, rem = i - ch * 324;
        int yy = rem / 18, xx = rem - yy * 18;
        int gy = y0 + yy, gx = x0 + xx;
        float v = 0.f;
        if ((unsigned)gy < 64u && (unsigned)gx < 64u) v = inp[ch * Nn + gy * 64 + gx];
        sin_[ch][yy][xx] = v;
    }
    __syncthreads();
    int ly = tid >> 4, lx = tid & 15;
    float o0 = 0.f, o1 = 0.f, o2 = 0.f, o3 = 0.f;
#pragma unroll
    for (int i = 0; i < 4; i++)
#pragma unroll
        for (int ky = 0; ky < 3; ky++)
#pragma unroll
            for (int kx = 0; kx < 3; kx++) {
                float v = sin_[i][ly + ky][lx + kx];
                o0 = fmaf(v, sw[0][i][ky * 3 + kx], o0);
                o1 = fmaf(v, sw[1][i][ky * 3 + kx], o1);
                o2 = fmaf(v, sw[2][i][ky * 3 + kx], o2);
                o3 = fmaf(v, sw[3][i][ky * 3 + kx], o3);
            }
    int oy = y0 + 1 + ly, ox = x0 + 1 + lx;
    float* op = g_cv + ((size_t)b * CD + g * 4) * Nn + oy * 64 + ox;
    op[0] = o0; op[Nn] = o1; op[2 * (size_t)Nn] = o2; op[3 * (size_t)Nn] = o3;
}

// ---------------- K4: row softmax over N + AB = softmax(dt+A)*BC ----------------
__global__ __launch_bounds__(256) void softmax_k(const float* __restrict__ A) {
    __shared__ float shm[8], shs[8];
    int b = blockIdx.y, s = blockIdx.x;
    const float* dt = g_cv + ((size_t)b * CD + S + s) * Nn;
    const float* BC = g_cv + ((size_t)b * CD + s) * Nn;
    float* out = g_AB + ((size_t)b * S + s) * Nn;
    int tid = threadIdx.x;
    float a = A[s];
    float v[16];
    float mx = -1e30f;
#pragma unroll
    for (int i = 0; i < 16; i++) {
        v[i] = dt[i * 256 + tid] + a;
        mx = fmaxf(mx, v[i]);
    }
#pragma unroll
    for (int o = 16; o; o >>= 1) mx = fmaxf(mx, __shfl_xor_sync(0xffffffffu, mx, o));
    if ((tid & 31) == 0) shm[tid >> 5] = mx;
    __syncthreads();
    if (tid == 0) {
        float m = shm[0];
        for (int i = 1; i < 8; i++) m = fmaxf(m, shm[i]);
        shm[0] = m;
    }
    __syncthreads();
    mx = shm[0];
    float sum = 0.f;
#pragma unroll
    for (int i = 0; i < 16; i++) { v[i] = __expf(v[i] - mx); sum += v[i]; }
#pragma unroll
    for (int o = 16; o; o >>= 1) sum += __shfl_xor_sync(0xffffffffu, sum, o);
    if ((tid & 31) == 0) shs[tid >> 5] = sum;
    __syncthreads();
    if (tid == 0) {
        float m = 0.f;
        for (int i = 0; i < 8; i++) m += shs[i];
        shs[0] = m;
    }
    __syncthreads();
    float invs = 1.f / shs[0];
#pragma unroll
    for (int i = 0; i < 16; i++) out[i * 256 + tid] = v[i] * invs * BC[i * 256 + tid];
}

// ---------------- K5: h = x @ AB^T  (256x64, K=4096) split-K=8, deterministic ----------------
__global__ __launch_bounds__(256) void hgemm_k(const float* __restrict__ x) {
    __shared__ float xs[16][65];
    __shared__ float as[16][65];
    int ks = blockIdx.x;             // split-K slice 0..7 (each 512 of K)
    int c0 = blockIdx.y * 64;        // M tile
    int b  = blockIdx.z;
    const float* xp  = x + (size_t)b * C * Nn;
    const float* abp = g_AB + (size_t)b * S * Nn;
    int tid = threadIdx.x;
    int tm = tid >> 4, tn = tid & 15;
    float acc[4][4] = {};
    int lm = tid >> 2, lk4 = (tid & 3) * 4;
    int kend = ks * 512 + 512;
    for (int kk = ks * 512; kk < kend; kk += 16) {
        float4 xv = *(const float4*)(xp  + (size_t)(c0 + lm) * Nn + kk + lk4);
        float4 av = *(const float4*)(abp + (size_t)lm        * Nn + kk + lk4);
        __syncthreads();
        xs[lk4 + 0][lm] = xv.x; xs[lk4 + 1][lm] = xv.y;
        xs[lk4 + 2][lm] = xv.z; xs[lk4 + 3][lm] = xv.w;
        as[lk4 + 0][lm] = av.x; as[lk4 + 1][lm] = av.y;
        as[lk4 + 2][lm] = av.z; as[lk4 + 3][lm] = av.w;
        __syncthreads();
#pragma unroll
        for (int k = 0; k < 16; k++) {
            float a[4], bb[4];
#pragma unroll
            for (int i = 0; i < 4; i++) a[i] = xs[k][tm * 4 + i];
#pragma unroll
            for (int j = 0; j < 4; j++) bb[j] = as[k][tn * 4 + j];
#pragma unroll
            for (int i = 0; i < 4; i++)
#pragma unroll
                for (int j = 0; j < 4; j++) acc[i][j] = fmaf(a[i], bb[j], acc[i][j]);
        }
    }
    float* hp = g_hpart[ks] + ((size_t)b * C + c0) * S;
#pragma unroll
    for (int i = 0; i < 4; i++)
#pragma unroll
        for (int j = 0; j < 4; j++)
            hp[(size_t)(tm * 4 + i) * S + tn * 4 + j] = acc[i][j];
}

// ---------------- K6: reduce split-K partials ----------------
__global__ void reduceh_k() {
    size_t i = (size_t)blockIdx.x * 256 + threadIdx.x;
    float s = 0.f;
#pragma unroll
    for (int p = 0; p < 8; p++) s += g_hpart[p][i];
    g_h[i] = s;
}

// ---------------- K7: h2 = w_out @ h  (256x64, K=256) ----------------
__global__ __launch_bounds__(256) void h2_k(const float* __restrict__ w_out) {
    __shared__ float ws[16][65];
    __shared__ float hs[16][68];
    int m0 = blockIdx.x * 64, b = blockIdx.y;
    const float* hp = g_h + (size_t)b * C * S;
    int tid = threadIdx.x;
    int tm = tid >> 4, tn = tid & 15;
    float acc[4][4] = {};
    int lm = tid >> 2, lk4 = (tid & 3) * 4;
    int hk = tid >> 4, hs4 = (tid & 15) * 4;
    for (int k0 = 0; k0 < C; k0 += 16) {
        float4 wv = *(const float4*)(w_out + (size_t)(m0 + lm) * C + k0 + lk4);
        float4 hv = *(const float4*)(hp + (size_t)(k0 + hk) * S + hs4);
        __syncthreads();
        ws[lk4 + 0][lm] = wv.x; ws[lk4 + 1][lm] = wv.y;
        ws[lk4 + 2][lm] = wv.z; ws[lk4 + 3][lm] = wv.w;
        hs[hk][hs4 + 0] = hv.x; hs[hk][hs4 + 1] = hv.y;
        hs[hk][hs4 + 2] = hv.z; hs[hk][hs4 + 3] = hv.w;
        __syncthreads();
#pragma unroll
        for (int k = 0; k < 16; k++) {
            float a[4], bb[4];
#pragma unroll
            for (int i = 0; i < 4; i++) a[i] = ws[k][tm * 4 + i];
#pragma unroll
            for (int j = 0; j < 4; j++) bb[j] = hs[k][tn * 4 + j];
#pragma unroll
            for (int i = 0; i < 4; i++)
#pragma unroll
                for (int j = 0; j < 4; j++) acc[i][j] = fmaf(a[i], bb[j], acc[i][j]);
        }
    }
    float* o = g_h2 + ((size_t)b * C + m0) * S;
#pragma unroll
    for (int i = 0; i < 4; i++)
#pragma unroll
        for (int j = 0; j < 4; j++)
            o[(size_t)(tm * 4 + i) * S + tn * 4 + j] = acc[i][j];
}

// ---------------- K8: out = h2 @ BC + x  (256x4096, K=64) ----------------
__global__ __launch_bounds__(256) void final_k(const float* __restrict__ x,
                                               float* __restrict__ out) {
    __shared__ float hs[16][65];   // [k][m]
    __shared__ float bs[16][129];  // [k][n]
    int n0 = blockIdx.x * 128, m0 = blockIdx.y * 64, b = blockIdx.z;
    const float* h2p = g_h2 + ((size_t)b * C + m0) * S;
    const float* bcp = g_cv + (size_t)b * CD * Nn;   // BC = rows 0..63
    int tid = threadIdx.x;
    int tm = tid >> 4, tn = tid & 15;
    float acc[4][8] = {};
    int lm = tid >> 2, lk4 = (tid & 3) * 4;
    int bk = tid >> 5, bn4 = (tid & 31) * 4;
    for (int k0 = 0; k0 < S; k0 += 16) {
        float4 hv = *(const float4*)(h2p + (size_t)lm * S + k0 + lk4);
        float4 b0 = *(const float4*)(bcp + (size_t)(k0 + bk) * Nn + n0 + bn4);
        float4 b1 = *(const float4*)(bcp + (size_t)(k0 + bk + 8) * Nn + n0 + bn4);
        __syncthreads();
        hs[lk4 + 0][lm] = hv.x; hs[lk4 + 1][lm] = hv.y;
        hs[lk4 + 2][lm] = hv.z; hs[lk4 + 3][lm] = hv.w;
        bs[bk][bn4 + 0] = b0.x; bs[bk][bn4 + 1] = b0.y;
        bs[bk][bn4 + 2] = b0.z; bs[bk][bn4 + 3] = b0.w;
        bs[bk + 8][bn4 + 0] = b1.x; bs[bk + 8][bn4 + 1] = b1.y;
        bs[bk + 8][bn4 + 2] = b1.z; bs[bk + 8][bn4 + 3] = b1.w;
        __syncthreads();
#pragma unroll
        for (int k = 0; k < 16; k++) {
            float a[4], bb[8];
#pragma unroll
            for (int i = 0; i < 4; i++) a[i] = hs[k][tm * 4 + i];
#pragma unroll
            for (int j = 0; j < 8; j++) bb[j] = bs[k][tn * 8 + j];
#pragma unroll
            for (int i = 0; i < 4; i++)
#pragma unroll
                for (int j = 0; j < 8; j++) acc[i][j] = fmaf(a[i], bb[j], acc[i][j]);
        }
    }
    const float* xp = x + ((size_t)b * C + m0) * Nn;
    float* op = out + ((size_t)b * C + m0) * Nn;
#pragma unroll
    for (int i = 0; i < 4; i++) {
        int m = tm * 4 + i;
#pragma unroll
        for (int j = 0; j < 8; j++) {
            int n = n0 + tn * 8 + j;
            op[(size_t)m * Nn + n] = acc[i][j] + xp[(size_t)m * Nn + n];
        }
    }
}

// ---------------- launcher ----------------
extern "C" void kernel_launch(void* const* d_in, const int* in_sizes, int n_in,
                              void* d_out, int out_size) {
    const float* x      = (const float*)d_in[0];
    const float* ln_w   = (const float*)d_in[1];
    const float* ln_b   = (const float*)d_in[2];
    const float* w_bcdt = (const float*)d_in[3];
    const float* w_gw   = (const float*)d_in[4];
    const float* w_out  = (const float*)d_in[5];
    const float* A      = (const float*)d_in[6];
    float* out = (float*)d_out;

    prep_w_k<<<128, 256>>>(w_bcdt, ln_w, ln_b);
    stats_k<<<(Bsz * Nn) / 256, 256>>>(x);
    gemm1_k<<<dim3(Nn / 128, Bsz), 256>>>(x);
    conv_k<<<dim3(16, 32, Bsz), 256>>>(w_gw);
    softmax_k<<<dim3(S, Bsz), 256>>>(A);
    hgemm_k<<<dim3(8, C / 64, Bsz), 256>>>(x);
    reduceh_k<<<(Bsz * C * S) / 256, 256>>>();
    h2_k<<<dim3(C / 64, Bsz), 256>>>(w_out);
    final_k<<<dim3(Nn / 128, C / 64, Bsz), 256>>>(x, out);
}

// round 3
// speedup vs baseline: 1.8495x; 1.8495x over previous
#include <cuda_runtime.h>
#include <cuda_bf16.h>
#include <cstdint>

static constexpr int Bsz = 32;
static constexpr int C   = 256;
static constexpr int Nn  = 4096;
static constexpr int S   = 64;
static constexpr int CD  = 128;
static constexpr float EPS = 1e-5f;

// ---------------- scratch ----------------
__device__ float g_mean[Bsz * Nn];
__device__ float g_inv [Bsz * Nn];
__device__ float g_rowsum[CD];
__device__ float g_bias  [CD];
__device__ __nv_bfloat16 g_wp_hi[CD * C], g_wp_lo[CD * C];
__device__ __nv_bfloat16 g_xt_hi[(size_t)Bsz * Nn * C];   // 64 MB
__device__ __nv_bfloat16 g_xt_lo[(size_t)Bsz * Nn * C];   // 64 MB
__device__ float g_bcdt[(size_t)Bsz * CD * Nn];
__device__ float g_cv  [(size_t)Bsz * CD * Nn];
__device__ __nv_bfloat16 g_ab_hi[(size_t)Bsz * S * Nn], g_ab_lo[(size_t)Bsz * S * Nn];
__device__ __nv_bfloat16 g_bct_hi[(size_t)Bsz * Nn * S], g_bct_lo[(size_t)Bsz * Nn * S];
__device__ float g_hpart[(size_t)8 * Bsz * C * S];
__device__ float g_h   [(size_t)Bsz * C * S];
__device__ float g_h2  [(size_t)Bsz * C * S];

// ---------------- helpers ----------------
#define SWZ(o) ((o) ^ (((o) >> 3) & 0x70))

__device__ __forceinline__ uint32_t smem_u32(const void* p) {
    uint32_t a;
    asm("{ .reg .u64 t; cvta.to.shared.u64 t, %1; cvt.u32.u64 %0, t; }" : "=r"(a) : "l"(p));
    return a;
}
__device__ __forceinline__ void ldmx4(uint32_t* r, uint32_t addr) {
    asm volatile("ldmatrix.sync.aligned.m8n8.x4.shared.b16 {%0,%1,%2,%3}, [%4];"
        : "=r"(r[0]), "=r"(r[1]), "=r"(r[2]), "=r"(r[3]) : "r"(addr));
}
__device__ __forceinline__ void mma16816(float* d, const uint32_t* a, const uint32_t* b) {
    asm volatile("mma.sync.aligned.m16n8k16.row.col.f32.bf16.bf16.f32 "
        "{%0,%1,%2,%3}, {%4,%5,%6,%7}, {%8,%9}, {%0,%1,%2,%3};"
        : "+f"(d[0]), "+f"(d[1]), "+f"(d[2]), "+f"(d[3])
        : "r"(a[0]), "r"(a[1]), "r"(a[2]), "r"(a[3]), "r"(b[0]), "r"(b[1]));
}
__device__ __forceinline__ uint32_t ldm_addr(uint32_t base, int rowbase, int lane, int kByte) {
    int o = (rowbase + (lane & 15)) * 128 + kByte + ((lane >> 4) * 16);
    return base + SWZ(o);
}
__device__ __forceinline__ uint32_t pk(__nv_bfloat16 a, __nv_bfloat16 b) {
    return (uint32_t)__bfloat16_as_ushort(a) | ((uint32_t)__bfloat16_as_ushort(b) << 16);
}
__device__ __forceinline__ void split_sc(float x, __nv_bfloat16& h, __nv_bfloat16& l) {
    h = __float2bfloat16(x);
    l = __float2bfloat16(x - __bfloat162float(h));
}
__device__ __forceinline__ void split_f4(float4 v, uint2& hi, uint2& lo) {
    __nv_bfloat16 hx, hy, hz, hw, lx, ly, lz, lw;
    split_sc(v.x, hx, lx); split_sc(v.y, hy, ly);
    split_sc(v.z, hz, lz); split_sc(v.w, hw, lw);
    hi.x = pk(hx, hy); hi.y = pk(hz, hw);
    lo.x = pk(lx, ly); lo.y = pk(lz, lw);
}

// ---------------- K0: fold LN into proj weights; emit bf16 planes ----------------
__global__ void prep_w_k(const float* __restrict__ w_bcdt,
                         const float* __restrict__ ln_w,
                         const float* __restrict__ ln_b) {
    int o = blockIdx.x, c = threadIdx.x;
    float w  = w_bcdt[o * C + c];
    float wp = w * ln_w[c];
    __nv_bfloat16 h, l; split_sc(wp, h, l);
    g_wp_hi[o * C + c] = h;
    g_wp_lo[o * C + c] = l;
    __shared__ float s1[256], s2[256];
    s1[c] = wp;
    s2[c] = w * ln_b[c];
    __syncthreads();
    for (int st = 128; st > 0; st >>= 1) {
        if (c < st) { s1[c] += s1[c + st]; s2[c] += s2[c + st]; }
        __syncthreads();
    }
    if (c == 0) { g_rowsum[o] = s1[0]; g_bias[o] = s2[0]; }
}

// ---------------- transpose x -> bf16 hi/lo planes [b][n][c] ----------------
__global__ void transpose_x_k(const float* __restrict__ x) {
    __shared__ float t[32][33];
    int n0 = blockIdx.x * 32, c0 = blockIdx.y * 32, b = blockIdx.z;
    int tx = threadIdx.x, ty = threadIdx.y;
#pragma unroll
    for (int i = 0; i < 4; i++)
        t[ty + i * 8][tx] = x[((size_t)b * C + c0 + ty + i * 8) * Nn + n0 + tx];
    __syncthreads();
#pragma unroll
    for (int i = 0; i < 4; i++) {
        float v = t[tx][ty + i * 8];
        __nv_bfloat16 h, l; split_sc(v, h, l);
        size_t idx = ((size_t)b * Nn + n0 + ty + i * 8) * C + c0 + tx;
        g_xt_hi[idx] = h;
        g_xt_lo[idx] = l;
    }
}

// ---------------- transpose BC -> bf16 hi/lo planes [b][n][s] ----------------
__global__ void transpose_bc_k() {
    __shared__ float t[32][33];
    int n0 = blockIdx.x * 32, s0 = blockIdx.y * 32, b = blockIdx.z;
    int tx = threadIdx.x, ty = threadIdx.y;
#pragma unroll
    for (int i = 0; i < 4; i++)
        t[ty + i * 8][tx] = g_cv[((size_t)b * CD + s0 + ty + i * 8) * Nn + n0 + tx];
    __syncthreads();
#pragma unroll
    for (int i = 0; i < 4; i++) {
        float v = t[tx][ty + i * 8];
        __nv_bfloat16 h, l; split_sc(v, h, l);
        size_t idx = ((size_t)b * Nn + n0 + ty + i * 8) * S + s0 + tx;
        g_bct_hi[idx] = h;
        g_bct_lo[idx] = l;
    }
}

// ---------------- stats ----------------
__global__ void stats_k(const float* __restrict__ x) {
    int idx = blockIdx.x * 256 + threadIdx.x;
    int b = idx >> 12, n = idx & 4095;
    const float* xp = x + (size_t)b * C * Nn + n;
    float s = 0.f, sq = 0.f;
#pragma unroll 8
    for (int c = 0; c < C; c++) {
        float v = xp[(size_t)c * Nn];
        s += v; sq = fmaf(v, v, sq);
    }
    float m   = s * (1.f / 256.f);
    float var = (sq - 256.f * m * m) * (1.f / 255.f);
    g_mean[idx] = m;
    g_inv[idx]  = rsqrtf(var + EPS);
}

// ---------------- GEMM1 (mma.sync bf16 3x): D[pix128, cd128], K=256 ----------------
__global__ __launch_bounds__(256) void gemm1_mma() {
    extern __shared__ char sm[];
    uint32_t sb = smem_u32(sm);
    const uint32_t OAH = 0, OAL = 16384, OBH = 32768, OBL = 49152;
    int tid = threadIdx.x, wid = tid >> 5, lane = tid & 31;
    int b = blockIdx.y, n0 = blockIdx.x * 128;
    int wm = wid & 1, wn = wid >> 1;
    float acc[4][4][4] = {};

    for (int p = 0; p < 4; p++) {
        if (p) __syncthreads();
#pragma unroll
        for (int i = 0; i < 4; i++) {
            int t = tid + i * 256;
            int row = t >> 3, ch = t & 7;
            uint32_t o = SWZ((uint32_t)(row * 128 + ch * 16));
            size_t asrc = ((size_t)(b * 4096 + n0 + row)) * 256 + p * 64 + ch * 8;
            *(uint4*)(sm + OAH + o) = *(const uint4*)(g_xt_hi + asrc);
            *(uint4*)(sm + OAL + o) = *(const uint4*)(g_xt_lo + asrc);
            size_t bsrc = (size_t)row * 256 + p * 64 + ch * 8;
            *(uint4*)(sm + OBH + o) = *(const uint4*)(g_wp_hi + bsrc);
            *(uint4*)(sm + OBL + o) = *(const uint4*)(g_wp_lo + bsrc);
        }
        __syncthreads();
#pragma unroll
        for (int ks = 0; ks < 4; ks++) {
            uint32_t ah[4][4], al[4][4], bh[4][2], bl[4][2];
#pragma unroll
            for (int mt = 0; mt < 4; mt++) {
                ldmx4(ah[mt], ldm_addr(sb + OAH, wm * 64 + mt * 16, lane, ks * 32));
                ldmx4(al[mt], ldm_addr(sb + OAL, wm * 64 + mt * 16, lane, ks * 32));
            }
#pragma unroll
            for (int bt = 0; bt < 2; bt++) {
                uint32_t r[4];
                ldmx4(r, ldm_addr(sb + OBH, wn * 32 + bt * 16, lane, ks * 32));
                bh[bt*2][0] = r[0]; bh[bt*2][1] = r[2]; bh[bt*2+1][0] = r[1]; bh[bt*2+1][1] = r[3];
                ldmx4(r, ldm_addr(sb + OBL, wn * 32 + bt * 16, lane, ks * 32));
                bl[bt*2][0] = r[0]; bl[bt*2][1] = r[2]; bl[bt*2+1][0] = r[1]; bl[bt*2+1][1] = r[3];
            }
#pragma unroll
            for (int mt = 0; mt < 4; mt++)
#pragma unroll
                for (int nt = 0; nt < 4; nt++) {
                    mma16816(acc[mt][nt], ah[mt], bh[nt]);
                    mma16816(acc[mt][nt], ah[mt], bl[nt]);
                    mma16816(acc[mt][nt], al[mt], bh[nt]);
                }
        }
    }
    // epilogue: g_bcdt[b][cd][pix] = inv*(acc - mean*rowsum) + bias
    int g = lane >> 2, tig = lane & 3;
    float rs[8], bi[8];
#pragma unroll
    for (int nt = 0; nt < 4; nt++) {
        int cd = wn * 32 + nt * 8 + tig * 2;
        rs[nt*2] = g_rowsum[cd];   bi[nt*2]   = g_bias[cd];
        rs[nt*2+1] = g_rowsum[cd+1]; bi[nt*2+1] = g_bias[cd+1];
    }
    float* outp = g_bcdt + ((size_t)b * CD) * Nn;
    const float* meanp = g_mean + b * Nn;
    const float* invp  = g_inv  + b * Nn;
#pragma unroll
    for (int mt = 0; mt < 4; mt++) {
        int ma = wm * 64 + mt * 16 + g;
        int pa = n0 + ma, pb = pa + 8;
        float mea = meanp[pa], iva = invp[pa];
        float meb = meanp[pb], ivb = invp[pb];
#pragma unroll
        for (int nt = 0; nt < 4; nt++) {
            int cd0 = wn * 32 + nt * 8 + tig * 2;
            float* o0 = outp + (size_t)cd0 * Nn;
            float* o1 = o0 + Nn;
            o0[pa] = iva * (acc[mt][nt][0] - mea * rs[nt*2])   + bi[nt*2];
            o1[pa] = iva * (acc[mt][nt][1] - mea * rs[nt*2+1]) + bi[nt*2+1];
            o0[pb] = ivb * (acc[mt][nt][2] - meb * rs[nt*2])   + bi[nt*2];
            o1[pb] = ivb * (acc[mt][nt][3] - meb * rs[nt*2+1]) + bi[nt*2+1];
        }
    }
}

// ---------------- grouped 3x3 conv: 4 horizontal outputs/thread ----------------
__global__ __launch_bounds__(256) void conv_k(const float* __restrict__ w_gw) {
    __shared__ float si[4][34][37];
    __shared__ float sw[4][4][9];
    int b = blockIdx.z, g = blockIdx.y, tile = blockIdx.x;
    int tid = threadIdx.x;
    if (tid < 144) {
        int o = tid / 36, r = tid % 36;
        sw[o][r / 9][r % 9] = w_gw[(g * 4 + o) * 36 + r];
    }
    const float* inp = g_bcdt + ((size_t)(b * CD + g * 4)) * Nn;
    int y0 = (tile >> 1) * 32 - 1, x0 = (tile & 1) * 32 - 1;
    for (int i = tid; i < 4 * 34 * 34; i += 256) {
        int ch = i / 1156, rem = i - ch * 1156;
        int yy = rem / 34, xx = rem - yy * 34;
        int gy = y0 + yy, gx = x0 + xx;
        float v = 0.f;
        if ((unsigned)gy < 64u && (unsigned)gx < 64u) v = inp[ch * Nn + gy * 64 + gx];
        si[ch][yy][xx] = v;
    }
    __syncthreads();
    int ly = tid >> 3, lx4 = (tid & 7) * 4;
    float acc[4][4] = {};
#pragma unroll
    for (int ch = 0; ch < 4; ch++)
#pragma unroll
        for (int ky = 0; ky < 3; ky++) {
            float r[6];
#pragma unroll
            for (int j = 0; j < 6; j++) r[j] = si[ch][ly + ky][lx4 + j];
#pragma unroll
            for (int o = 0; o < 4; o++) {
                float w0 = sw[o][ch][ky*3], w1 = sw[o][ch][ky*3+1], w2 = sw[o][ch][ky*3+2];
#pragma unroll
                for (int px = 0; px < 4; px++)
                    acc[o][px] = fmaf(r[px], w0, fmaf(r[px+1], w1, fmaf(r[px+2], w2, acc[o][px])));
            }
        }
    int oy = y0 + 1 + ly, ox = x0 + 1 + lx4;
    float* op = g_cv + ((size_t)(b * CD + g * 4)) * Nn + oy * 64 + ox;
#pragma unroll
    for (int o = 0; o < 4; o++)
        *(float4*)(op + (size_t)o * Nn) = make_float4(acc[o][0], acc[o][1], acc[o][2], acc[o][3]);
}

// ---------------- softmax + AB -> bf16 hi/lo planes ----------------
__global__ __launch_bounds__(256) void softmax_k(const float* __restrict__ A) {
    __shared__ float shm[8], shs[8];
    int b = blockIdx.y, s = blockIdx.x;
    const float* dt = g_cv + ((size_t)b * CD + S + s) * Nn;
    const float* BC = g_cv + ((size_t)b * CD + s) * Nn;
    size_t obase = ((size_t)b * S + s) * Nn;
    int tid = threadIdx.x;
    float a = A[s];
    float v[16];
    float mx = -1e30f;
#pragma unroll
    for (int i = 0; i < 16; i++) {
        v[i] = dt[i * 256 + tid] + a;
        mx = fmaxf(mx, v[i]);
    }
#pragma unroll
    for (int o = 16; o; o >>= 1) mx = fmaxf(mx, __shfl_xor_sync(0xffffffffu, mx, o));
    if ((tid & 31) == 0) shm[tid >> 5] = mx;
    __syncthreads();
    if (tid == 0) {
        float m = shm[0];
        for (int i = 1; i < 8; i++) m = fmaxf(m, shm[i]);
        shm[0] = m;
    }
    __syncthreads();
    mx = shm[0];
    float sum = 0.f;
#pragma unroll
    for (int i = 0; i < 16; i++) { v[i] = __expf(v[i] - mx); sum += v[i]; }
#pragma unroll
    for (int o = 16; o; o >>= 1) sum += __shfl_xor_sync(0xffffffffu, sum, o);
    if ((tid & 31) == 0) shs[tid >> 5] = sum;
    __syncthreads();
    if (tid == 0) {
        float m = 0.f;
        for (int i = 0; i < 8; i++) m += shs[i];
        shs[0] = m;
    }
    __syncthreads();
    float invs = 1.f / shs[0];
#pragma unroll
    for (int i = 0; i < 16; i++) {
        float val = v[i] * invs * BC[i * 256 + tid];
        __nv_bfloat16 h, l; split_sc(val, h, l);
        g_ab_hi[obase + i * 256 + tid] = h;
        g_ab_lo[obase + i * 256 + tid] = l;
    }
}

// ---------------- hgemm (mma): h[c128, s64] partials, K=512/block ----------------
__global__ __launch_bounds__(256) void hgemm_mma(const float* __restrict__ x) {
    extern __shared__ char sm[];
    uint32_t sb = smem_u32(sm);
    const uint32_t OAH = 0, OAL = 16384, OBH = 32768, OBL = 40960;
    int tid = threadIdx.x, wid = tid >> 5, lane = tid & 31;
    int ks = blockIdx.x, mh = blockIdx.y, b = blockIdx.z;
    int wm = wid & 3, wn = wid >> 2;
    float acc[2][4][4] = {};

    for (int p = 0; p < 8; p++) {
        if (p) __syncthreads();
#pragma unroll
        for (int i = 0; i < 8; i++) {
            int t = tid + i * 256;
            int row = t >> 4, q = t & 15;
            float4 v = *(const float4*)(x + ((size_t)(b * 256 + mh * 128 + row)) * 4096
                                          + ks * 512 + p * 64 + q * 4);
            uint2 hi, lo; split_f4(v, hi, lo);
            uint32_t o = SWZ((uint32_t)(row * 128 + q * 8));
            *(uint2*)(sm + OAH + o) = hi;
            *(uint2*)(sm + OAL + o) = lo;
        }
#pragma unroll
        for (int i = 0; i < 2; i++) {
            int t = tid + i * 256;
            int row = t >> 3, ch = t & 7;
            size_t src = ((size_t)(b * 64 + row)) * 4096 + ks * 512 + p * 64 + ch * 8;
            uint32_t o = SWZ((uint32_t)(row * 128 + ch * 16));
            *(uint4*)(sm + OBH + o) = *(const uint4*)(g_ab_hi + src);
            *(uint4*)(sm + OBL + o) = *(const uint4*)(g_ab_lo + src);
        }
        __syncthreads();
#pragma unroll
        for (int kk = 0; kk < 4; kk++) {
            uint32_t ah[2][4], al[2][4], bh[4][2], bl[4][2];
#pragma unroll
            for (int mt = 0; mt < 2; mt++) {
                ldmx4(ah[mt], ldm_addr(sb + OAH, wm * 32 + mt * 16, lane, kk * 32));
                ldmx4(al[mt], ldm_addr(sb + OAL, wm * 32 + mt * 16, lane, kk * 32));
            }
#pragma unroll
            for (int bt = 0; bt < 2; bt++) {
                uint32_t r[4];
                ldmx4(r, ldm_addr(sb + OBH, wn * 32 + bt * 16, lane, kk * 32));
                bh[bt*2][0] = r[0]; bh[bt*2][1] = r[2]; bh[bt*2+1][0] = r[1]; bh[bt*2+1][1] = r[3];
                ldmx4(r, ldm_addr(sb + OBL, wn * 32 + bt * 16, lane, kk * 32));
                bl[bt*2][0] = r[0]; bl[bt*2][1] = r[2]; bl[bt*2+1][0] = r[1]; bl[bt*2+1][1] = r[3];
            }
#pragma unroll
            for (int mt = 0; mt < 2; mt++)
#pragma unroll
                for (int nt = 0; nt < 4; nt++) {
                    mma16816(acc[mt][nt], ah[mt], bh[nt]);
                    mma16816(acc[mt][nt], ah[mt], bl[nt]);
                    mma16816(acc[mt][nt], al[mt], bh[nt]);
                }
        }
    }
    int g = lane >> 2, tig = lane & 3;
    float* hp = g_hpart + (size_t)ks * (Bsz * C * S) + ((size_t)(b * 256 + mh * 128)) * 64;
#pragma unroll
    for (int mt = 0; mt < 2; mt++) {
        int ca = wm * 32 + mt * 16 + g;
#pragma unroll
        for (int nt = 0; nt < 4; nt++) {
            int s0 = wn * 32 + nt * 8 + tig * 2;
            *(float2*)(hp + (size_t)ca * 64 + s0)       = make_float2(acc[mt][nt][0], acc[mt][nt][1]);
            *(float2*)(hp + (size_t)(ca + 8) * 64 + s0) = make_float2(acc[mt][nt][2], acc[mt][nt][3]);
        }
    }
}

// ---------------- reduce split-K partials ----------------
__global__ void reduceh_k() {
    size_t i = (size_t)blockIdx.x * 256 + threadIdx.x;
    float s = 0.f;
#pragma unroll
    for (int p = 0; p < 8; p++) s += g_hpart[(size_t)p * (Bsz * C * S) + i];
    g_h[i] = s;
}

// ---------------- h2 = w_out @ h (fp32, tiny) ----------------
__global__ __launch_bounds__(256) void h2_k(const float* __restrict__ w_out) {
    __shared__ float ws[16][65];
    __shared__ float hs[16][68];
    int m0 = blockIdx.x * 64, b = blockIdx.y;
    const float* hp = g_h + (size_t)b * C * S;
    int tid = threadIdx.x;
    int tm = tid >> 4, tn = tid & 15;
    float acc[4][4] = {};
    int lm = tid >> 2, lk4 = (tid & 3) * 4;
    int hk = tid >> 4, hs4 = (tid & 15) * 4;
    for (int k0 = 0; k0 < C; k0 += 16) {
        float4 wv = *(const float4*)(w_out + (size_t)(m0 + lm) * C + k0 + lk4);
        float4 hv = *(const float4*)(hp + (size_t)(k0 + hk) * S + hs4);
        __syncthreads();
        ws[lk4 + 0][lm] = wv.x; ws[lk4 + 1][lm] = wv.y;
        ws[lk4 + 2][lm] = wv.z; ws[lk4 + 3][lm] = wv.w;
        hs[hk][hs4 + 0] = hv.x; hs[hk][hs4 + 1] = hv.y;
        hs[hk][hs4 + 2] = hv.z; hs[hk][hs4 + 3] = hv.w;
        __syncthreads();
#pragma unroll
        for (int k = 0; k < 16; k++) {
            float a[4], bb[4];
#pragma unroll
            for (int i = 0; i < 4; i++) a[i] = ws[k][tm * 4 + i];
#pragma unroll
            for (int j = 0; j < 4; j++) bb[j] = hs[k][tn * 4 + j];
#pragma unroll
            for (int i = 0; i < 4; i++)
#pragma unroll
                for (int j = 0; j < 4; j++) acc[i][j] = fmaf(a[i], bb[j], acc[i][j]);
        }
    }
    float* o = g_h2 + ((size_t)b * C + m0) * S;
#pragma unroll
    for (int i = 0; i < 4; i++)
#pragma unroll
        for (int j = 0; j < 4; j++)
            o[(size_t)(tm * 4 + i) * S + tn * 4 + j] = acc[i][j];
}

// ---------------- final (mma): out[c128, pix128] = h2 @ bct^T + x ----------------
__global__ __launch_bounds__(256) void final_mma(const float* __restrict__ x,
                                                 float* __restrict__ out) {
    extern __shared__ char sm[];
    uint32_t sb = smem_u32(sm);
    const uint32_t OAH = 0, OAL = 16384, OBH = 32768, OBL = 49152;
    int tid = threadIdx.x, wid = tid >> 5, lane = tid & 31;
    int n0 = blockIdx.x * 128, mh = blockIdx.y, b = blockIdx.z;
    int wm = wid & 1, wn = wid >> 1;
    float acc[4][4][4] = {};

    // A = h2[c][s] fp32 -> split
#pragma unroll
    for (int i = 0; i < 8; i++) {
        int t = tid + i * 256;
        int row = t >> 4, q = t & 15;
        float4 v = *(const float4*)(g_h2 + ((size_t)(b * 256 + mh * 128 + row)) * 64 + q * 4);
        uint2 hi, lo; split_f4(v, hi, lo);
        uint32_t o = SWZ((uint32_t)(row * 128 + q * 8));
        *(uint2*)(sm + OAH + o) = hi;
        *(uint2*)(sm + OAL + o) = lo;
    }
    // B = bct[pix][s] bf16 planes
#pragma unroll
    for (int i = 0; i < 4; i++) {
        int t = tid + i * 256;
        int row = t >> 3, ch = t & 7;
        size_t src = ((size_t)(b * 4096 + n0 + row)) * 64 + ch * 8;
        uint32_t o = SWZ((uint32_t)(row * 128 + ch * 16));
        *(uint4*)(sm + OBH + o) = *(const uint4*)(g_bct_hi + src);
        *(uint4*)(sm + OBL + o) = *(const uint4*)(g_bct_lo + src);
    }
    __syncthreads();
#pragma unroll
    for (int kk = 0; kk < 4; kk++) {
        uint32_t ah[4][4], al[4][4], bh[4][2], bl[4][2];
#pragma unroll
        for (int mt = 0; mt < 4; mt++) {
            ldmx4(ah[mt], ldm_addr(sb + OAH, wm * 64 + mt * 16, lane, kk * 32));
            ldmx4(al[mt], ldm_addr(sb + OAL, wm * 64 + mt * 16, lane, kk * 32));
        }
#pragma unroll
        for (int bt = 0; bt < 2; bt++) {
            uint32_t r[4];
            ldmx4(r, ldm_addr(sb + OBH, wn * 32 + bt * 16, lane, kk * 32));
            bh[bt*2][0] = r[0]; bh[bt*2][1] = r[2]; bh[bt*2+1][0] = r[1]; bh[bt*2+1][1] = r[3];
            ldmx4(r, ldm_addr(sb + OBL, wn * 32 + bt * 16, lane, kk * 32));
            bl[bt*2][0] = r[0]; bl[bt*2][1] = r[2]; bl[bt*2+1][0] = r[1]; bl[bt*2+1][1] = r[3];
        }
#pragma unroll
        for (int mt = 0; mt < 4; mt++)
#pragma unroll
            for (int nt = 0; nt < 4; nt++) {
                mma16816(acc[mt][nt], ah[mt], bh[nt]);
                mma16816(acc[mt][nt], ah[mt], bl[nt]);
                mma16816(acc[mt][nt], al[mt], bh[nt]);
            }
    }
    int g = lane >> 2, tig = lane & 3;
#pragma unroll
    for (int mt = 0; mt < 4; mt++) {
        int ca = wm * 64 + mt * 16 + g;
        size_t ra = ((size_t)(b * 256 + mh * 128 + ca)) * 4096 + n0;
        size_t rb = ra + (size_t)8 * 4096;
#pragma unroll
        for (int nt = 0; nt < 4; nt++) {
            int px = wn * 32 + nt * 8 + tig * 2;
            float2 xa = *(const float2*)(x + ra + px);
            float2 xb = *(const float2*)(x + rb + px);
            *(float2*)(out + ra + px) = make_float2(acc[mt][nt][0] + xa.x, acc[mt][nt][1] + xa.y);
            *(float2*)(out + rb + px) = make_float2(acc[mt][nt][2] + xb.x, acc[mt][nt][3] + xb.y);
        }
    }
}

// ---------------- launcher ----------------
extern "C" void kernel_launch(void* const* d_in, const int* in_sizes, int n_in,
                              void* d_out, int out_size) {
    const float* x      = (const float*)d_in[0];
    const float* ln_w   = (const float*)d_in[1];
    const float* ln_b   = (const float*)d_in[2];
    const float* w_bcdt = (const float*)d_in[3];
    const float* w_gw   = (const float*)d_in[4];
    const float* w_out  = (const float*)d_in[5];
    const float* A      = (const float*)d_in[6];
    float* out = (float*)d_out;

    cudaFuncSetAttribute(gemm1_mma, cudaFuncAttributeMaxDynamicSharedMemorySize, 65536);
    cudaFuncSetAttribute(hgemm_mma, cudaFuncAttributeMaxDynamicSharedMemorySize, 49152);
    cudaFuncSetAttribute(final_mma, cudaFuncAttributeMaxDynamicSharedMemorySize, 65536);

    prep_w_k<<<128, 256>>>(w_bcdt, ln_w, ln_b);
    transpose_x_k<<<dim3(128, 8, Bsz), dim3(32, 8)>>>(x);
    stats_k<<<(Bsz * Nn) / 256, 256>>>(x);
    gemm1_mma<<<dim3(32, Bsz), 256, 65536>>>();
    conv_k<<<dim3(4, 32, Bsz), 256>>>(w_gw);
    softmax_k<<<dim3(S, Bsz), 256>>>(A);
    hgemm_mma<<<dim3(8, 2, Bsz), 256, 49152>>>(x);
    reduceh_k<<<(Bsz * C * S) / 256, 256>>>();
    h2_k<<<dim3(C / 64, Bsz), 256>>>(w_out);
    transpose_bc_k<<<dim3(128, 2, Bsz), dim3(32, 8)>>>();
    final_mma<<<dim3(32, 2, Bsz), 256, 65536>>>(x, out);
}

// round 4
// speedup vs baseline: 2.1819x; 1.1798x over previous
#include <cuda_runtime.h>
#include <cuda_bf16.h>
#include <cstdint>

static constexpr int Bsz = 32;
static constexpr int C   = 256;
static constexpr int Nn  = 4096;
static constexpr int S   = 64;
static constexpr int CD  = 128;
static constexpr float EPS = 1e-5f;

// ---------------- scratch ----------------
__device__ float g_mean[Bsz * Nn];
__device__ float g_inv [Bsz * Nn];
__device__ float g_rowsum[CD];
__device__ float g_bias  [CD];
__device__ __nv_bfloat16 g_wp_hi[CD * C], g_wp_lo[CD * C];
__device__ float g_bcdt[(size_t)Bsz * CD * Nn];
__device__ float g_cv  [(size_t)Bsz * CD * Nn];
__device__ __nv_bfloat16 g_ab_hi[(size_t)Bsz * S * Nn], g_ab_lo[(size_t)Bsz * S * Nn];
__device__ float g_hpart[(size_t)8 * Bsz * C * S];
__device__ float g_h   [(size_t)Bsz * C * S];
__device__ float g_h2  [(size_t)Bsz * C * S];

// ---------------- helpers ----------------
#define SWZ(o) ((o) ^ (((o) >> 3) & 0x70))

__device__ __forceinline__ uint32_t smem_u32(const void* p) {
    uint32_t a;
    asm("{ .reg .u64 t; cvta.to.shared.u64 t, %1; cvt.u32.u64 %0, t; }" : "=r"(a) : "l"(p));
    return a;
}
__device__ __forceinline__ void ldmx4(uint32_t* r, uint32_t addr) {
    asm volatile("ldmatrix.sync.aligned.m8n8.x4.shared.b16 {%0,%1,%2,%3}, [%4];"
        : "=r"(r[0]), "=r"(r[1]), "=r"(r[2]), "=r"(r[3]) : "r"(addr));
}
__device__ __forceinline__ void ldmx4t(uint32_t* r, uint32_t addr) {
    asm volatile("ldmatrix.sync.aligned.m8n8.x4.trans.shared.b16 {%0,%1,%2,%3}, [%4];"
        : "=r"(r[0]), "=r"(r[1]), "=r"(r[2]), "=r"(r[3]) : "r"(addr));
}
__device__ __forceinline__ void mma16816(float* d, const uint32_t* a, const uint32_t* b) {
    asm volatile("mma.sync.aligned.m16n8k16.row.col.f32.bf16.bf16.f32 "
        "{%0,%1,%2,%3}, {%4,%5,%6,%7}, {%8,%9}, {%0,%1,%2,%3};"
        : "+f"(d[0]), "+f"(d[1]), "+f"(d[2]), "+f"(d[3])
        : "r"(a[0]), "r"(a[1]), "r"(a[2]), "r"(a[3]), "r"(b[0]), "r"(b[1]));
}
__device__ __forceinline__ uint32_t ldm_addr(uint32_t base, int rowbase, int lane, int kByte) {
    int o = (rowbase + (lane & 15)) * 128 + kByte + ((lane >> 4) * 16);
    return base + SWZ(o);
}
__device__ __forceinline__ void cp16(uint32_t dst, const void* src) {
    asm volatile("cp.async.ca.shared.global [%0], [%1], 16;" :: "r"(dst), "l"(src));
}
#define CP_COMMIT asm volatile("cp.async.commit_group;" ::: "memory")
#define CP_WAIT0  asm volatile("cp.async.wait_group 0;" ::: "memory")

__device__ __forceinline__ uint32_t pk(__nv_bfloat16 a, __nv_bfloat16 b) {
    return (uint32_t)__bfloat16_as_ushort(a) | ((uint32_t)__bfloat16_as_ushort(b) << 16);
}
__device__ __forceinline__ void split_sc(float x, __nv_bfloat16& h, __nv_bfloat16& l) {
    h = __float2bfloat16(x);
    l = __float2bfloat16(x - __bfloat162float(h));
}
__device__ __forceinline__ void split_f4(float4 v, uint2& hi, uint2& lo) {
    __nv_bfloat16 hx, hy, hz, hw, lx, ly, lz, lw;
    split_sc(v.x, hx, lx); split_sc(v.y, hy, ly);
    split_sc(v.z, hz, lz); split_sc(v.w, hw, lw);
    hi.x = pk(hx, hy); hi.y = pk(hz, hw);
    lo.x = pk(lx, ly); lo.y = pk(lz, lw);
}

// ---------------- K0: fold LN into proj weights ----------------
__global__ void prep_w_k(const float* __restrict__ w_bcdt,
                         const float* __restrict__ ln_w,
                         const float* __restrict__ ln_b) {
    int o = blockIdx.x, c = threadIdx.x;
    float w  = w_bcdt[o * C + c];
    float wp = w * ln_w[c];
    __nv_bfloat16 h, l; split_sc(wp, h, l);
    g_wp_hi[o * C + c] = h;
    g_wp_lo[o * C + c] = l;
    __shared__ float s1[256], s2[256];
    s1[c] = wp;
    s2[c] = w * ln_b[c];
    __syncthreads();
    for (int st = 128; st > 0; st >>= 1) {
        if (c < st) { s1[c] += s1[c + st]; s2[c] += s2[c + st]; }
        __syncthreads();
    }
    if (c == 0) { g_rowsum[o] = s1[0]; g_bias[o] = s2[0]; }
}

// ---------------- stats ----------------
__global__ void stats_k(const float* __restrict__ x) {
    int idx = blockIdx.x * 256 + threadIdx.x;
    int b = idx >> 12, n = idx & 4095;
    const float* xp = x + (size_t)b * C * Nn + n;
    float s = 0.f, sq = 0.f;
#pragma unroll 8
    for (int c = 0; c < C; c++) {
        float v = xp[(size_t)c * Nn];
        s += v; sq = fmaf(v, v, sq);
    }
    float m   = s * (1.f / 256.f);
    float var = (sq - 256.f * m * m) * (1.f / 255.f);
    g_mean[idx] = m;
    g_inv[idx]  = rsqrtf(var + EPS);
}

// ---------------- GEMM1: D[cd128][pix128] = Wp * x, K=256; double buffered ----------------
// A = Wp planes (cp.async, K-major). B = x (inline fp32->bf16 split, ldmatrix.trans).
__global__ __launch_bounds__(256) void gemm1_mma(const float* __restrict__ x) {
    extern __shared__ char sm[];
    uint32_t sb = smem_u32(sm);
    const uint32_t OA = 0, OB = 65536;   // A: 2 buf x (16K hi + 16K lo); B at 65536: 2 buf x (16K hi + 16K lo)
    int tid = threadIdx.x, wid = tid >> 5, lane = tid & 31;
    int b = blockIdx.y, n0 = blockIdx.x * 128;
    int wm = wid & 1, wn = wid >> 1;
    const float* xg = x + (size_t)b * C * Nn;
    float acc[4][4][4] = {};
    float4 xr[8];

    auto issueA = [&](int p, int buf) {
        uint32_t da = sb + OA + buf * 32768;
#pragma unroll
        for (int i = 0; i < 4; i++) {
            int idx = tid + i * 256;
            int cd = idx >> 3, c8 = idx & 7;
            uint32_t off = SWZ((uint32_t)(cd * 128 + c8 * 16));
            cp16(da + off,         g_wp_hi + cd * 256 + p * 64 + c8 * 8);
            cp16(da + 16384 + off, g_wp_lo + cd * 256 + p * 64 + c8 * 8);
        }
    };
    auto loadX = [&](int p) {
#pragma unroll
        for (int i = 0; i < 8; i++) {
            int idx = tid + i * 256;
            int c = idx >> 5, pix4 = idx & 31;
            xr[i] = *(const float4*)(xg + (size_t)(p * 64 + c) * Nn + n0 + pix4 * 4);
        }
    };
    auto storeX = [&](int buf) {
        char* db = sm + OB + buf * 32768;
#pragma unroll
        for (int i = 0; i < 8; i++) {
            int idx = tid + i * 256;
            int c = idx >> 5, pix4 = idx & 31;
            uint2 hi, lo; split_f4(xr[i], hi, lo);
            uint32_t off = (uint32_t)((pix4 >> 4) * 8192) + SWZ((uint32_t)(c * 128 + (pix4 & 15) * 8));
            *(uint2*)(db + off)         = hi;
            *(uint2*)(db + 16384 + off) = lo;
        }
    };
    auto compute = [&](int buf) {
        uint32_t aB = sb + OA + buf * 32768;
        uint32_t bB = sb + OB + buf * 32768 + (uint32_t)((wn >> 1) * 8192);
        int pb2 = (wn & 1) * 64;   // pixel-base*2 within subtile
#pragma unroll
        for (int kk = 0; kk < 4; kk++) {
            uint32_t ah[4][4], al[4][4], bh[4][2], bl[4][2];
#pragma unroll
            for (int mt = 0; mt < 4; mt++) {
                ldmx4(ah[mt], ldm_addr(aB,         wm * 64 + mt * 16, lane, kk * 32));
                ldmx4(al[mt], ldm_addr(aB + 16384, wm * 64 + mt * 16, lane, kk * 32));
            }
#pragma unroll
            for (int bt = 0; bt < 2; bt++) {
                uint32_t r[4];
                ldmx4t(r, ldm_addr(bB, kk * 16, lane, pb2 + bt * 32));
                bh[bt*2][0] = r[0]; bh[bt*2][1] = r[1];
                bh[bt*2+1][0] = r[2]; bh[bt*2+1][1] = r[3];
                ldmx4t(r, ldm_addr(bB + 16384, kk * 16, lane, pb2 + bt * 32));
                bl[bt*2][0] = r[0]; bl[bt*2][1] = r[1];
                bl[bt*2+1][0] = r[2]; bl[bt*2+1][1] = r[3];
            }
#pragma unroll
            for (int mt = 0; mt < 4; mt++)
#pragma unroll
                for (int nt = 0; nt < 4; nt++) {
                    mma16816(acc[mt][nt], ah[mt], bh[nt]);
                    mma16816(acc[mt][nt], ah[mt], bl[nt]);
                    mma16816(acc[mt][nt], al[mt], bh[nt]);
                }
        }
    };

    issueA(0, 0); loadX(0); storeX(0);
    CP_COMMIT; CP_WAIT0;
    __syncthreads();
    for (int p = 0; p < 4; p++) {
        int buf = p & 1;
        if (p < 3) { issueA(p + 1, buf ^ 1); loadX(p + 1); }
        compute(buf);
        if (p < 3) {
            storeX(buf ^ 1);
            CP_COMMIT; CP_WAIT0;
            __syncthreads();
        }
    }

    // epilogue: g_bcdt[b][cd][pix] = inv*(acc - mean*rowsum) + bias
    int g = lane >> 2, tig = lane & 3;
    const float* meanp = g_mean + b * Nn + n0;
    const float* invp  = g_inv  + b * Nn + n0;
    float* outp = g_bcdt + (size_t)b * CD * Nn + n0;
    float me[4][2], iv[4][2];
    int px[4];
#pragma unroll
    for (int nt = 0; nt < 4; nt++) {
        px[nt] = wn * 32 + nt * 8 + tig * 2;
        me[nt][0] = meanp[px[nt]];     iv[nt][0] = invp[px[nt]];
        me[nt][1] = meanp[px[nt] + 1]; iv[nt][1] = invp[px[nt] + 1];
    }
#pragma unroll
    for (int mt = 0; mt < 4; mt++) {
        int cd0 = wm * 64 + mt * 16 + g, cd1 = cd0 + 8;
        float rs0 = g_rowsum[cd0], bi0 = g_bias[cd0];
        float rs1 = g_rowsum[cd1], bi1 = g_bias[cd1];
#pragma unroll
        for (int nt = 0; nt < 4; nt++) {
            float2 v0 = make_float2(
                iv[nt][0] * (acc[mt][nt][0] - me[nt][0] * rs0) + bi0,
                iv[nt][1] * (acc[mt][nt][1] - me[nt][1] * rs0) + bi0);
            float2 v1 = make_float2(
                iv[nt][0] * (acc[mt][nt][2] - me[nt][0] * rs1) + bi1,
                iv[nt][1] * (acc[mt][nt][3] - me[nt][1] * rs1) + bi1);
            *(float2*)(outp + (size_t)cd0 * Nn + px[nt]) = v0;
            *(float2*)(outp + (size_t)cd1 * Nn + px[nt]) = v1;
        }
    }
}

// ---------------- grouped 3x3 conv ----------------
__global__ __launch_bounds__(256) void conv_k(const float* __restrict__ w_gw) {
    __shared__ float si[4][34][37];
    __shared__ float sw[4][4][9];
    int b = blockIdx.z, g = blockIdx.y, tile = blockIdx.x;
    int tid = threadIdx.x;
    if (tid < 144) {
        int o = tid / 36, r = tid % 36;
        sw[o][r / 9][r % 9] = w_gw[(g * 4 + o) * 36 + r];
    }
    const float* inp = g_bcdt + ((size_t)(b * CD + g * 4)) * Nn;
    int y0 = (tile >> 1) * 32 - 1, x0 = (tile & 1) * 32 - 1;
    for (int i = tid; i < 4 * 34 * 34; i += 256) {
        int ch = i / 1156, rem = i - ch * 1156;
        int yy = rem / 34, xx = rem - yy * 34;
        int gy = y0 + yy, gx = x0 + xx;
        float v = 0.f;
        if ((unsigned)gy < 64u && (unsigned)gx < 64u) v = inp[ch * Nn + gy * 64 + gx];
        si[ch][yy][xx] = v;
    }
    __syncthreads();
    int ly = tid >> 3, lx4 = (tid & 7) * 4;
    float acc[4][4] = {};
#pragma unroll
    for (int ch = 0; ch < 4; ch++)
#pragma unroll
        for (int ky = 0; ky < 3; ky++) {
            float r[6];
#pragma unroll
            for (int j = 0; j < 6; j++) r[j] = si[ch][ly + ky][lx4 + j];
#pragma unroll
            for (int o = 0; o < 4; o++) {
                float w0 = sw[o][ch][ky*3], w1 = sw[o][ch][ky*3+1], w2 = sw[o][ch][ky*3+2];
#pragma unroll
                for (int p = 0; p < 4; p++)
                    acc[o][p] = fmaf(r[p], w0, fmaf(r[p+1], w1, fmaf(r[p+2], w2, acc[o][p])));
            }
        }
    int oy = y0 + 1 + ly, ox = x0 + 1 + lx4;
    float* op = g_cv + ((size_t)(b * CD + g * 4)) * Nn + oy * 64 + ox;
#pragma unroll
    for (int o = 0; o < 4; o++)
        *(float4*)(op + (size_t)o * Nn) = make_float4(acc[o][0], acc[o][1], acc[o][2], acc[o][3]);
}

// ---------------- softmax + AB -> bf16 planes ----------------
__global__ __launch_bounds__(256) void softmax_k(const float* __restrict__ A) {
    __shared__ float shm[8], shs[8];
    int b = blockIdx.y, s = blockIdx.x;
    const float* dt = g_cv + ((size_t)b * CD + S + s) * Nn;
    const float* BC = g_cv + ((size_t)b * CD + s) * Nn;
    size_t obase = ((size_t)b * S + s) * Nn;
    int tid = threadIdx.x;
    float a = A[s];
    float v[16];
    float mx = -1e30f;
#pragma unroll
    for (int i = 0; i < 16; i++) {
        v[i] = dt[i * 256 + tid] + a;
        mx = fmaxf(mx, v[i]);
    }
#pragma unroll
    for (int o = 16; o; o >>= 1) mx = fmaxf(mx, __shfl_xor_sync(0xffffffffu, mx, o));
    if ((tid & 31) == 0) shm[tid >> 5] = mx;
    __syncthreads();
    if (tid == 0) {
        float m = shm[0];
        for (int i = 1; i < 8; i++) m = fmaxf(m, shm[i]);
        shm[0] = m;
    }
    __syncthreads();
    mx = shm[0];
    float sum = 0.f;
#pragma unroll
    for (int i = 0; i < 16; i++) { v[i] = __expf(v[i] - mx); sum += v[i]; }
#pragma unroll
    for (int o = 16; o; o >>= 1) sum += __shfl_xor_sync(0xffffffffu, sum, o);
    if ((tid & 31) == 0) shs[tid >> 5] = sum;
    __syncthreads();
    if (tid == 0) {
        float m = 0.f;
        for (int i = 0; i < 8; i++) m += shs[i];
        shs[0] = m;
    }
    __syncthreads();
    float invs = 1.f / shs[0];
#pragma unroll
    for (int i = 0; i < 16; i++) {
        float val = v[i] * invs * BC[i * 256 + tid];
        __nv_bfloat16 h, l; split_sc(val, h, l);
        g_ab_hi[obase + i * 256 + tid] = h;
        g_ab_lo[obase + i * 256 + tid] = l;
    }
}

// ---------------- hgemm: h[c128][s64] partials, K=512/block; double buffered ----------------
__global__ __launch_bounds__(256) void hgemm_mma(const float* __restrict__ x) {
    extern __shared__ char sm[];
    uint32_t sb = smem_u32(sm);
    const uint32_t OA = 0, OB = 65536;   // A: 2 buf x 32K (hi16+lo16); B: 2 buf x 16K (hi8+lo8)
    int tid = threadIdx.x, wid = tid >> 5, lane = tid & 31;
    int ks = blockIdx.x, mh = blockIdx.y, b = blockIdx.z;
    int wm = wid & 3, wn = wid >> 2;
    const float* xg = x + (size_t)(b * 256 + mh * 128) * Nn + ks * 512;
    float acc[2][4][4] = {};
    float4 ar[8];

    auto issueB = [&](int p, int buf) {
        uint32_t db = sb + OB + buf * 16384;
#pragma unroll
        for (int i = 0; i < 2; i++) {
            int idx = tid + i * 256;
            int s = idx >> 3, k8 = idx & 7;
            uint32_t off = SWZ((uint32_t)(s * 128 + k8 * 16));
            const size_t src = (size_t)(b * 64 + s) * Nn + ks * 512 + p * 64 + k8 * 8;
            cp16(db + off,        g_ab_hi + src);
            cp16(db + 8192 + off, g_ab_lo + src);
        }
    };
    auto loadA = [&](int p) {
#pragma unroll
        for (int i = 0; i < 8; i++) {
            int idx = tid + i * 256;
            int row = idx >> 4, q = idx & 15;
            ar[i] = *(const float4*)(xg + (size_t)row * Nn + p * 64 + q * 4);
        }
    };
    auto storeA = [&](int buf) {
        char* da = sm + OA + buf * 32768;
#pragma unroll
        for (int i = 0; i < 8; i++) {
            int idx = tid + i * 256;
            int row = idx >> 4, q = idx & 15;
            uint2 hi, lo; split_f4(ar[i], hi, lo);
            uint32_t off = SWZ((uint32_t)(row * 128 + q * 8));
            *(uint2*)(da + off)         = hi;
            *(uint2*)(da + 16384 + off) = lo;
        }
    };
    auto compute = [&](int buf) {
        uint32_t aB = sb + OA + buf * 32768;
        uint32_t bB = sb + OB + buf * 16384;
#pragma unroll
        for (int kk = 0; kk < 4; kk++) {
            uint32_t ah[2][4], al[2][4], bh[4][2], bl[4][2];
#pragma unroll
            for (int mt = 0; mt < 2; mt++) {
                ldmx4(ah[mt], ldm_addr(aB,         wm * 32 + mt * 16, lane, kk * 32));
                ldmx4(al[mt], ldm_addr(aB + 16384, wm * 32 + mt * 16, lane, kk * 32));
            }
#pragma unroll
            for (int bt = 0; bt < 2; bt++) {
                uint32_t r[4];
                ldmx4(r, ldm_addr(bB, wn * 32 + bt * 16, lane, kk * 32));
                bh[bt*2][0] = r[0]; bh[bt*2][1] = r[2];
                bh[bt*2+1][0] = r[1]; bh[bt*2+1][1] = r[3];
                ldmx4(r, ldm_addr(bB + 8192, wn * 32 + bt * 16, lane, kk * 32));
                bl[bt*2][0] = r[0]; bl[bt*2][1] = r[2];
                bl[bt*2+1][0] = r[1]; bl[bt*2+1][1] = r[3];
            }
#pragma unroll
            for (int mt = 0; mt < 2; mt++)
#pragma unroll
                for (int nt = 0; nt < 4; nt++) {
                    mma16816(acc[mt][nt], ah[mt], bh[nt]);
                    mma16816(acc[mt][nt], ah[mt], bl[nt]);
                    mma16816(acc[mt][nt], al[mt], bh[nt]);
                }
        }
    };

    issueB(0, 0); loadA(0); storeA(0);
    CP_COMMIT; CP_WAIT0;
    __syncthreads();
    for (int p = 0; p < 8; p++) {
        int buf = p & 1;
        if (p < 7) { issueB(p + 1, buf ^ 1); loadA(p + 1); }
        compute(buf);
        if (p < 7) {
            storeA(buf ^ 1);
            CP_COMMIT; CP_WAIT0;
            __syncthreads();
        }
    }

    int g = lane >> 2, tig = lane & 3;
    float* hp = g_hpart + (size_t)ks * (Bsz * C * S) + (size_t)(b * 256 + mh * 128) * 64;
#pragma unroll
    for (int mt = 0; mt < 2; mt++) {
        int ca = wm * 32 + mt * 16 + g;
#pragma unroll
        for (int nt = 0; nt < 4; nt++) {
            int s0 = wn * 32 + nt * 8 + tig * 2;
            *(float2*)(hp + (size_t)ca * 64 + s0)       = make_float2(acc[mt][nt][0], acc[mt][nt][1]);
            *(float2*)(hp + (size_t)(ca + 8) * 64 + s0) = make_float2(acc[mt][nt][2], acc[mt][nt][3]);
        }
    }
}

// ---------------- reduce split-K partials ----------------
__global__ void reduceh_k() {
    size_t i = (size_t)blockIdx.x * 256 + threadIdx.x;
    float s = 0.f;
#pragma unroll
    for (int p = 0; p < 8; p++) s += g_hpart[(size_t)p * (Bsz * C * S) + i];
    g_h[i] = s;
}

// ---------------- h2 = w_out @ h (fp32, tiny) ----------------
__global__ __launch_bounds__(256) void h2_k(const float* __restrict__ w_out) {
    __shared__ float ws[16][65];
    __shared__ float hs[16][68];
    int m0 = blockIdx.x * 64, b = blockIdx.y;
    const float* hp = g_h + (size_t)b * C * S;
    int tid = threadIdx.x;
    int tm = tid >> 4, tn = tid & 15;
    float acc[4][4] = {};
    int lm = tid >> 2, lk4 = (tid & 3) * 4;
    int hk = tid >> 4, hs4 = (tid & 15) * 4;
    for (int k0 = 0; k0 < C; k0 += 16) {
        float4 wv = *(const float4*)(w_out + (size_t)(m0 + lm) * C + k0 + lk4);
        float4 hv = *(const float4*)(hp + (size_t)(k0 + hk) * S + hs4);
        __syncthreads();
        ws[lk4 + 0][lm] = wv.x; ws[lk4 + 1][lm] = wv.y;
        ws[lk4 + 2][lm] = wv.z; ws[lk4 + 3][lm] = wv.w;
        hs[hk][hs4 + 0] = hv.x; hs[hk][hs4 + 1] = hv.y;
        hs[hk][hs4 + 2] = hv.z; hs[hk][hs4 + 3] = hv.w;
        __syncthreads();
#pragma unroll
        for (int k = 0; k < 16; k++) {
            float a[4], bb[4];
#pragma unroll
            for (int i = 0; i < 4; i++) a[i] = ws[k][tm * 4 + i];
#pragma unroll
            for (int j = 0; j < 4; j++) bb[j] = hs[k][tn * 4 + j];
#pragma unroll
            for (int i = 0; i < 4; i++)
#pragma unroll
                for (int j = 0; j < 4; j++) acc[i][j] = fmaf(a[i], bb[j], acc[i][j]);
        }
    }
    float* o = g_h2 + ((size_t)b * C + m0) * S;
#pragma unroll
    for (int i = 0; i < 4; i++)
#pragma unroll
        for (int j = 0; j < 4; j++)
            o[(size_t)(tm * 4 + i) * S + tn * 4 + j] = acc[i][j];
}

// ---------------- final: out[c128][pix128] = h2 @ BC + x; K=64 ----------------
// A = h2 (inline split, K-major). B = BC rows of g_cv (inline split, ldmatrix.trans).
__global__ __launch_bounds__(256) void final_mma(const float* __restrict__ x,
                                                 float* __restrict__ out) {
    extern __shared__ char sm[];
    uint32_t sb = smem_u32(sm);
    const uint32_t OAH = 0, OAL = 16384, OBH = 32768, OBL = 49152;
    int tid = threadIdx.x, wid = tid >> 5, lane = tid & 31;
    int n0 = blockIdx.x * 128, mh = blockIdx.y, b = blockIdx.z;
    int wm = wid & 1, wn = wid >> 1;
    float acc[4][4][4] = {};

    // A = h2[c][s]: 128x64 fp32
    float4 ar[8], br[8];
#pragma unroll
    for (int i = 0; i < 8; i++) {
        int idx = tid + i * 256;
        int row = idx >> 4, q = idx & 15;
        ar[i] = *(const float4*)(g_h2 + (size_t)(b * 256 + mh * 128 + row) * 64 + q * 4);
    }
    // B = BC[s][pix]: 64x128 fp32
#pragma unroll
    for (int i = 0; i < 8; i++) {
        int idx = tid + i * 256;
        int s = idx >> 5, pix4 = idx & 31;
        br[i] = *(const float4*)(g_cv + (size_t)(b * CD + s) * Nn + n0 + pix4 * 4);
    }
#pragma unroll
    for (int i = 0; i < 8; i++) {
        int idx = tid + i * 256;
        int row = idx >> 4, q = idx & 15;
        uint2 hi, lo; split_f4(ar[i], hi, lo);
        uint32_t off = SWZ((uint32_t)(row * 128 + q * 8));
        *(uint2*)(sm + OAH + off) = hi;
        *(uint2*)(sm + OAL + off) = lo;
    }
#pragma unroll
    for (int i = 0; i < 8; i++) {
        int idx = tid + i * 256;
        int s = idx >> 5, pix4 = idx & 31;
        uint2 hi, lo; split_f4(br[i], hi, lo);
        uint32_t off = (uint32_t)((pix4 >> 4) * 8192) + SWZ((uint32_t)(s * 128 + (pix4 & 15) * 8));
        *(uint2*)(sm + OBH + off) = hi;
        *(uint2*)(sm + OBL + off) = lo;
    }
    __syncthreads();

    uint32_t bB = sb + OBH + (uint32_t)((wn >> 1) * 8192);
    int pb2 = (wn & 1) * 64;
#pragma unroll
    for (int kk = 0; kk < 4; kk++) {
        uint32_t ah[4][4], al[4][4], bh[4][2], bl[4][2];
#pragma unroll
        for (int mt = 0; mt < 4; mt++) {
            ldmx4(ah[mt], ldm_addr(sb + OAH, wm * 64 + mt * 16, lane, kk * 32));
            ldmx4(al[mt], ldm_addr(sb + OAL, wm * 64 + mt * 16, lane, kk * 32));
        }
#pragma unroll
        for (int bt = 0; bt < 2; bt++) {
            uint32_t r[4];
            ldmx4t(r, ldm_addr(bB, kk * 16, lane, pb2 + bt * 32));
            bh[bt*2][0] = r[0]; bh[bt*2][1] = r[1];
            bh[bt*2+1][0] = r[2]; bh[bt*2+1][1] = r[3];
            ldmx4t(r, ldm_addr(bB + 16384, kk * 16, lane, pb2 + bt * 32));
            bl[bt*2][0] = r[0]; bl[bt*2][1] = r[1];
            bl[bt*2+1][0] = r[2]; bl[bt*2+1][1] = r[3];
        }
#pragma unroll
        for (int mt = 0; mt < 4; mt++)
#pragma unroll
            for (int nt = 0; nt < 4; nt++) {
                mma16816(acc[mt][nt], ah[mt], bh[nt]);
                mma16816(acc[mt][nt], ah[mt], bl[nt]);
                mma16816(acc[mt][nt], al[mt], bh[nt]);
            }
    }
    int g = lane >> 2, tig = lane & 3;
#pragma unroll
    for (int mt = 0; mt < 4; mt++) {
        int ca = wm * 64 + mt * 16 + g;
        size_t ra = (size_t)(b * 256 + mh * 128 + ca) * Nn + n0;
        size_t rb = ra + (size_t)8 * Nn;
#pragma unroll
        for (int nt = 0; nt < 4; nt++) {
            int px = wn * 32 + nt * 8 + tig * 2;
            float2 xa = *(const float2*)(x + ra + px);
            float2 xb = *(const float2*)(x + rb + px);
            *(float2*)(out + ra + px) = make_float2(acc[mt][nt][0] + xa.x, acc[mt][nt][1] + xa.y);
            *(float2*)(out + rb + px) = make_float2(acc[mt][nt][2] + xb.x, acc[mt][nt][3] + xb.y);
        }
    }
}

// ---------------- launcher ----------------
extern "C" void kernel_launch(void* const* d_in, const int* in_sizes, int n_in,
                              void* d_out, int out_size) {
    const float* x      = (const float*)d_in[0];
    const float* ln_w   = (const float*)d_in[1];
    const float* ln_b   = (const float*)d_in[2];
    const float* w_bcdt = (const float*)d_in[3];
    const float* w_gw   = (const float*)d_in[4];
    const float* w_out  = (const float*)d_in[5];
    const float* A      = (const float*)d_in[6];
    float* out = (float*)d_out;

    cudaFuncSetAttribute(gemm1_mma, cudaFuncAttributeMaxDynamicSharedMemorySize, 131072);
    cudaFuncSetAttribute(hgemm_mma, cudaFuncAttributeMaxDynamicSharedMemorySize, 98304);
    cudaFuncSetAttribute(final_mma, cudaFuncAttributeMaxDynamicSharedMemorySize, 65536);

    prep_w_k<<<128, 256>>>(w_bcdt, ln_w, ln_b);
    stats_k<<<(Bsz * Nn) / 256, 256>>>(x);
    gemm1_mma<<<dim3(32, Bsz), 256, 131072>>>(x);
    conv_k<<<dim3(4, 32, Bsz), 256>>>(w_gw);
    softmax_k<<<dim3(S, Bsz), 256>>>(A);
    hgemm_mma<<<dim3(8, 2, Bsz), 256, 98304>>>(x);
    reduceh_k<<<(Bsz * C * S) / 256, 256>>>();
    h2_k<<<dim3(C / 64, Bsz), 256>>>(w_out);
    final_mma<<<dim3(32, 2, Bsz), 256, 65536>>>(x, out);
}

// round 6
// speedup vs baseline: 2.3001x; 1.0541x over previous
#include <cuda_runtime.h>
#include <cuda_bf16.h>
#include <cstdint>

static constexpr int Bsz = 32;
static constexpr int C   = 256;
static constexpr int Nn  = 4096;
static constexpr int S   = 64;
static constexpr int CD  = 128;
static constexpr float EPS = 1e-5f;

// ---------------- scratch ----------------
__device__ float g_rowsum[CD];
__device__ float g_bias  [CD];
__device__ __nv_bfloat16 g_wp_hi[CD * C], g_wp_lo[CD * C];
__device__ float g_bcdt[(size_t)Bsz * CD * Nn];
__device__ float g_cv  [(size_t)Bsz * CD * Nn];
__device__ __nv_bfloat16 g_ab_hi[(size_t)Bsz * S * Nn], g_ab_lo[(size_t)Bsz * S * Nn];
__device__ float g_hpart[(size_t)8 * Bsz * C * S];
__device__ float g_h2  [(size_t)Bsz * C * S];

// ---------------- helpers ----------------
#define SWZ(o) ((o) ^ (((o) >> 3) & 0x70))

__device__ __forceinline__ uint32_t smem_u32(const void* p) {
    uint32_t a;
    asm("{ .reg .u64 t; cvta.to.shared.u64 t, %1; cvt.u32.u64 %0, t; }" : "=r"(a) : "l"(p));
    return a;
}
__device__ __forceinline__ void ldmx4(uint32_t* r, uint32_t addr) {
    asm volatile("ldmatrix.sync.aligned.m8n8.x4.shared.b16 {%0,%1,%2,%3}, [%4];"
        : "=r"(r[0]), "=r"(r[1]), "=r"(r[2]), "=r"(r[3]) : "r"(addr));
}
__device__ __forceinline__ void ldmx4t(uint32_t* r, uint32_t addr) {
    asm volatile("ldmatrix.sync.aligned.m8n8.x4.trans.shared.b16 {%0,%1,%2,%3}, [%4];"
        : "=r"(r[0]), "=r"(r[1]), "=r"(r[2]), "=r"(r[3]) : "r"(addr));
}
__device__ __forceinline__ void mma16816(float* d, const uint32_t* a, const uint32_t* b) {
    asm volatile("mma.sync.aligned.m16n8k16.row.col.f32.bf16.bf16.f32 "
        "{%0,%1,%2,%3}, {%4,%5,%6,%7}, {%8,%9}, {%0,%1,%2,%3};"
        : "+f"(d[0]), "+f"(d[1]), "+f"(d[2]), "+f"(d[3])
        : "r"(a[0]), "r"(a[1]), "r"(a[2]), "r"(a[3]), "r"(b[0]), "r"(b[1]));
}
__device__ __forceinline__ uint32_t ldm_addr(uint32_t base, int rowbase, int lane, int kByte) {
    int o = (rowbase + (lane & 15)) * 128 + kByte + ((lane >> 4) * 16);
    return base + SWZ(o);
}
__device__ __forceinline__ void cp16(uint32_t dst, const void* src) {
    asm volatile("cp.async.ca.shared.global [%0], [%1], 16;" :: "r"(dst), "l"(src));
}
#define CP_COMMIT asm volatile("cp.async.commit_group;" ::: "memory")
#define CP_WAIT0  asm volatile("cp.async.wait_group 0;" ::: "memory")

__device__ __forceinline__ uint32_t pk(__nv_bfloat16 a, __nv_bfloat16 b) {
    return (uint32_t)__bfloat16_as_ushort(a) | ((uint32_t)__bfloat16_as_ushort(b) << 16);
}
__device__ __forceinline__ void split_sc(float x, __nv_bfloat16& h, __nv_bfloat16& l) {
    h = __float2bfloat16(x);
    l = __float2bfloat16(x - __bfloat162float(h));
}
__device__ __forceinline__ void split_f4(float4 v, uint2& hi, uint2& lo) {
    __nv_bfloat16 hx, hy, hz, hw, lx, ly, lz, lw;
    split_sc(v.x, hx, lx); split_sc(v.y, hy, ly);
    split_sc(v.z, hz, lz); split_sc(v.w, hw, lw);
    hi.x = pk(hx, hy); hi.y = pk(hz, hw);
    lo.x = pk(lx, ly); lo.y = pk(lz, lw);
}

// ---------------- K0: fold LN into proj weights ----------------
__global__ void prep_w_k(const float* __restrict__ w_bcdt,
                         const float* __restrict__ ln_w,
                         const float* __restrict__ ln_b) {
    int o = blockIdx.x, c = threadIdx.x;
    float w  = w_bcdt[o * C + c];
    float wp = w * ln_w[c];
    __nv_bfloat16 h, l; split_sc(wp, h, l);
    g_wp_hi[o * C + c] = h;
    g_wp_lo[o * C + c] = l;
    __shared__ float s1[256], s2[256];
    s1[c] = wp;
    s2[c] = w * ln_b[c];
    __syncthreads();
    for (int st = 128; st > 0; st >>= 1) {
        if (c < st) { s1[c] += s1[c + st]; s2[c] += s2[c + st]; }
        __syncthreads();
    }
    if (c == 0) { g_rowsum[o] = s1[0]; g_bias[o] = s2[0]; }
}

// ---------------- GEMM1: D[cd128][pix128] = Wp * x, K=256; fused LN stats ----------------
__global__ __launch_bounds__(256) void gemm1_mma(const float* __restrict__ x) {
    extern __shared__ char sm[];
    __shared__ float sm_mean[128], sm_inv[128];
    uint32_t sb = smem_u32(sm);
    const uint32_t OA = 0, OB = 65536;
    int tid = threadIdx.x, wid = tid >> 5, lane = tid & 31;
    int b = blockIdx.y, n0 = blockIdx.x * 128;
    int wm = wid & 1, wn = wid >> 1;
    const float* xg = x + (size_t)b * C * Nn;
    float acc[4][4][4] = {};
    float4 xr[8];
    float sacc[4] = {}, sqacc[4] = {};

    auto issueA = [&](int p, int buf) {
        uint32_t da = sb + OA + buf * 32768;
#pragma unroll
        for (int i = 0; i < 4; i++) {
            int idx = tid + i * 256;
            int cd = idx >> 3, c8 = idx & 7;
            uint32_t off = SWZ((uint32_t)(cd * 128 + c8 * 16));
            cp16(da + off,         g_wp_hi + cd * 256 + p * 64 + c8 * 8);
            cp16(da + 16384 + off, g_wp_lo + cd * 256 + p * 64 + c8 * 8);
        }
    };
    auto loadX = [&](int p) {
#pragma unroll
        for (int i = 0; i < 8; i++) {
            int idx = tid + i * 256;
            int c = idx >> 5, pix4 = idx & 31;
            float4 v = *(const float4*)(xg + (size_t)(p * 64 + c) * Nn + n0 + pix4 * 4);
            xr[i] = v;
            sacc[0] += v.x; sqacc[0] = fmaf(v.x, v.x, sqacc[0]);
            sacc[1] += v.y; sqacc[1] = fmaf(v.y, v.y, sqacc[1]);
            sacc[2] += v.z; sqacc[2] = fmaf(v.z, v.z, sqacc[2]);
            sacc[3] += v.w; sqacc[3] = fmaf(v.w, v.w, sqacc[3]);
        }
    };
    auto storeX = [&](int buf) {
        char* db = sm + OB + buf * 32768;
#pragma unroll
        for (int i = 0; i < 8; i++) {
            int idx = tid + i * 256;
            int c = idx >> 5, pix4 = idx & 31;
            uint2 hi, lo; split_f4(xr[i], hi, lo);
            uint32_t off = (uint32_t)((pix4 >> 4) * 8192) + SWZ((uint32_t)(c * 128 + (pix4 & 15) * 8));
            *(uint2*)(db + off)         = hi;
            *(uint2*)(db + 16384 + off) = lo;
        }
    };
    auto compute = [&](int buf) {
        uint32_t aB = sb + OA + buf * 32768;
        uint32_t bB = sb + OB + buf * 32768 + (uint32_t)((wn >> 1) * 8192);
        int pb2 = (wn & 1) * 64;
#pragma unroll
        for (int kk = 0; kk < 4; kk++) {
            uint32_t ah[4][4], al[4][4], bh[4][2], bl[4][2];
#pragma unroll
            for (int mt = 0; mt < 4; mt++) {
                ldmx4(ah[mt], ldm_addr(aB,         wm * 64 + mt * 16, lane, kk * 32));
                ldmx4(al[mt], ldm_addr(aB + 16384, wm * 64 + mt * 16, lane, kk * 32));
            }
#pragma unroll
            for (int bt = 0; bt < 2; bt++) {
                uint32_t r[4];
                ldmx4t(r, ldm_addr(bB, kk * 16, lane, pb2 + bt * 32));
                bh[bt*2][0] = r[0]; bh[bt*2][1] = r[1];
                bh[bt*2+1][0] = r[2]; bh[bt*2+1][1] = r[3];
                ldmx4t(r, ldm_addr(bB + 16384, kk * 16, lane, pb2 + bt * 32));
                bl[bt*2][0] = r[0]; bl[bt*2][1] = r[1];
                bl[bt*2+1][0] = r[2]; bl[bt*2+1][1] = r[3];
            }
#pragma unroll
            for (int mt = 0; mt < 4; mt++)
#pragma unroll
                for (int nt = 0; nt < 4; nt++) {
                    mma16816(acc[mt][nt], ah[mt], bh[nt]);
                    mma16816(acc[mt][nt], ah[mt], bl[nt]);
                    mma16816(acc[mt][nt], al[mt], bh[nt]);
                }
        }
    };

    issueA(0, 0); loadX(0); storeX(0);
    CP_COMMIT; CP_WAIT0;
    __syncthreads();
    for (int p = 0; p < 4; p++) {
        int buf = p & 1;
        if (p < 3) { issueA(p + 1, buf ^ 1); loadX(p + 1); }
        compute(buf);
        if (p < 3) {
            storeX(buf ^ 1);
            CP_COMMIT; CP_WAIT0;
            __syncthreads();
        }
    }

    // --- fused LN stats: reduce per-pixel sums across thread groups ---
    __syncthreads();                       // compute() done reading smem
    float* red = (float*)sm;               // repurpose 8KB
    {
        int r8 = tid >> 5, p4 = (tid & 31) * 4;
#pragma unroll
        for (int j = 0; j < 4; j++) {
            red[r8 * 128 + p4 + j]        = sacc[j];
            red[1024 + r8 * 128 + p4 + j] = sqacc[j];
        }
    }
    __syncthreads();
    if (tid < 128) {
        float s = 0.f, q = 0.f;
#pragma unroll
        for (int r = 0; r < 8; r++) {
            s += red[r * 128 + tid];
            q += red[1024 + r * 128 + tid];
        }
        float m = s * (1.f / 256.f);
        float var = (q - 256.f * m * m) * (1.f / 255.f);
        sm_mean[tid] = m;
        sm_inv[tid]  = rsqrtf(var + EPS);
    }
    __syncthreads();

    // epilogue
    int g = lane >> 2, tig = lane & 3;
    float* outp = g_bcdt + (size_t)b * CD * Nn + n0;
    float me[4][2], iv[4][2];
    int px[4];
#pragma unroll
    for (int nt = 0; nt < 4; nt++) {
        px[nt] = wn * 32 + nt * 8 + tig * 2;
        me[nt][0] = sm_mean[px[nt]];     iv[nt][0] = sm_inv[px[nt]];
        me[nt][1] = sm_mean[px[nt] + 1]; iv[nt][1] = sm_inv[px[nt] + 1];
    }
#pragma unroll
    for (int mt = 0; mt < 4; mt++) {
        int cd0 = wm * 64 + mt * 16 + g, cd1 = cd0 + 8;
        float rs0 = g_rowsum[cd0], bi0 = g_bias[cd0];
        float rs1 = g_rowsum[cd1], bi1 = g_bias[cd1];
#pragma unroll
        for (int nt = 0; nt < 4; nt++) {
            float2 v0 = make_float2(
                iv[nt][0] * (acc[mt][nt][0] - me[nt][0] * rs0) + bi0,
                iv[nt][1] * (acc[mt][nt][1] - me[nt][1] * rs0) + bi0);
            float2 v1 = make_float2(
                iv[nt][0] * (acc[mt][nt][2] - me[nt][0] * rs1) + bi1,
                iv[nt][1] * (acc[mt][nt][3] - me[nt][1] * rs1) + bi1);
            *(float2*)(outp + (size_t)cd0 * Nn + px[nt]) = v0;
            *(float2*)(outp + (size_t)cd1 * Nn + px[nt]) = v1;
        }
    }
}

// ---------------- grouped 3x3 conv: full-width strips, aligned smem ----------------
// Row layout: [72] floats; data at cols [4..67], left halo col 3, right halo col 68.
__global__ __launch_bounds__(256) void conv_k(const float* __restrict__ w_gw) {
    __shared__ float si[4][34][72];
    __shared__ float sw[4][4][9];
    int b = blockIdx.z, g = blockIdx.y, ys = blockIdx.x;   // ys: 0..1
    int tid = threadIdx.x;
    if (tid < 144) {
        int o = tid / 36, r = tid % 36;
        sw[o][r / 9][r % 9] = w_gw[(g * 4 + o) * 36 + r];
    }
    const float* inp = g_bcdt + ((size_t)(b * CD + g * 4)) * Nn;
    int y0 = ys * 32;
    // zero x-halo columns
    if (tid < 136) {
        int ch = tid / 34, row = tid % 34;
        si[ch][row][3]  = 0.f;
        si[ch][row][68] = 0.f;
    }
    // load 34 full-width rows per channel, float4-coalesced (col 4 + c4 is 16B-aligned)
#pragma unroll
    for (int ch = 0; ch < 4; ch++) {
        for (int j = tid; j < 34 * 16; j += 256) {
            int row = j >> 4, c4 = (j & 15) * 4;
            int gy = y0 - 1 + row;
            float4 v = make_float4(0.f, 0.f, 0.f, 0.f);
            if ((unsigned)gy < 64u) v = *(const float4*)(inp + ch * Nn + gy * 64 + c4);
            *(float4*)(&si[ch][row][4 + c4]) = v;
        }
    }
    __syncthreads();
    int ly = tid >> 3, lx8 = (tid & 7) * 8;
    float acc[4][8] = {};
#pragma unroll
    for (int ch = 0; ch < 4; ch++)
#pragma unroll
        for (int ky = 0; ky < 3; ky++) {
            float r[10];
#pragma unroll
            for (int j = 0; j < 10; j++) r[j] = si[ch][ly + ky][3 + lx8 + j];
#pragma unroll
            for (int o = 0; o < 4; o++) {
                float w0 = sw[o][ch][ky*3], w1 = sw[o][ch][ky*3+1], w2 = sw[o][ch][ky*3+2];
#pragma unroll
                for (int p = 0; p < 8; p++)
                    acc[o][p] = fmaf(r[p], w0, fmaf(r[p+1], w1, fmaf(r[p+2], w2, acc[o][p])));
            }
        }
    float* op = g_cv + ((size_t)(b * CD + g * 4)) * Nn + (y0 + ly) * 64 + lx8;
#pragma unroll
    for (int o = 0; o < 4; o++) {
        *(float4*)(op + (size_t)o * Nn)     = make_float4(acc[o][0], acc[o][1], acc[o][2], acc[o][3]);
        *(float4*)(op + (size_t)o * Nn + 4) = make_float4(acc[o][4], acc[o][5], acc[o][6], acc[o][7]);
    }
}

// ---------------- softmax + AB -> bf16 planes ----------------
__global__ __launch_bounds__(256) void softmax_k(const float* __restrict__ A) {
    __shared__ float shm[8], shs[8];
    int b = blockIdx.y, s = blockIdx.x;
    const float* dt = g_cv + ((size_t)b * CD + S + s) * Nn;
    const float* BC = g_cv + ((size_t)b * CD + s) * Nn;
    size_t obase = ((size_t)b * S + s) * Nn;
    int tid = threadIdx.x;
    float a = A[s];
    float v[16];
    float mx = -1e30f;
#pragma unroll
    for (int i = 0; i < 16; i++) {
        v[i] = dt[i * 256 + tid] + a;
        mx = fmaxf(mx, v[i]);
    }
#pragma unroll
    for (int o = 16; o; o >>= 1) mx = fmaxf(mx, __shfl_xor_sync(0xffffffffu, mx, o));
    if ((tid & 31) == 0) shm[tid >> 5] = mx;
    __syncthreads();
    if (tid == 0) {
        float m = shm[0];
        for (int i = 1; i < 8; i++) m = fmaxf(m, shm[i]);
        shm[0] = m;
    }
    __syncthreads();
    mx = shm[0];
    float sum = 0.f;
#pragma unroll
    for (int i = 0; i < 16; i++) { v[i] = __expf(v[i] - mx); sum += v[i]; }
#pragma unroll
    for (int o = 16; o; o >>= 1) sum += __shfl_xor_sync(0xffffffffu, sum, o);
    if ((tid & 31) == 0) shs[tid >> 5] = sum;
    __syncthreads();
    if (tid == 0) {
        float m = 0.f;
        for (int i = 0; i < 8; i++) m += shs[i];
        shs[0] = m;
    }
    __syncthreads();
    float invs = 1.f / shs[0];
#pragma unroll
    for (int i = 0; i < 16; i++) {
        float val = v[i] * invs * BC[i * 256 + tid];
        __nv_bfloat16 h, l; split_sc(val, h, l);
        g_ab_hi[obase + i * 256 + tid] = h;
        g_ab_lo[obase + i * 256 + tid] = l;
    }
}

// ---------------- hgemm: h[c128][s64] partials, K=512/block; double buffered ----------------
__global__ __launch_bounds__(256) void hgemm_mma(const float* __restrict__ x) {
    extern __shared__ char sm[];
    uint32_t sb = smem_u32(sm);
    const uint32_t OA = 0, OB = 65536;
    int tid = threadIdx.x, wid = tid >> 5, lane = tid & 31;
    int ks = blockIdx.x, mh = blockIdx.y, b = blockIdx.z;
    int wm = wid & 3, wn = wid >> 2;
    const float* xg = x + (size_t)(b * 256 + mh * 128) * Nn + ks * 512;
    float acc[2][4][4] = {};
    float4 ar[8];

    auto issueB = [&](int p, int buf) {
        uint32_t db = sb + OB + buf * 16384;
#pragma unroll
        for (int i = 0; i < 2; i++) {
            int idx = tid + i * 256;
            int s = idx >> 3, k8 = idx & 7;
            uint32_t off = SWZ((uint32_t)(s * 128 + k8 * 16));
            const size_t src = (size_t)(b * 64 + s) * Nn + ks * 512 + p * 64 + k8 * 8;
            cp16(db + off,        g_ab_hi + src);
            cp16(db + 8192 + off, g_ab_lo + src);
        }
    };
    auto loadA = [&](int p) {
#pragma unroll
        for (int i = 0; i < 8; i++) {
            int idx = tid + i * 256;
            int row = idx >> 4, q = idx & 15;
            ar[i] = *(const float4*)(xg + (size_t)row * Nn + p * 64 + q * 4);
        }
    };
    auto storeA = [&](int buf) {
        char* da = sm + OA + buf * 32768;
#pragma unroll
        for (int i = 0; i < 8; i++) {
            int idx = tid + i * 256;
            int row = idx >> 4, q = idx & 15;
            uint2 hi, lo; split_f4(ar[i], hi, lo);
            uint32_t off = SWZ((uint32_t)(row * 128 + q * 8));
            *(uint2*)(da + off)         = hi;
            *(uint2*)(da + 16384 + off) = lo;
        }
    };
    auto compute = [&](int buf) {
        uint32_t aB = sb + OA + buf * 32768;
        uint32_t bB = sb + OB + buf * 16384;
#pragma unroll
        for (int kk = 0; kk < 4; kk++) {
            uint32_t ah[2][4], al[2][4], bh[4][2], bl[4][2];
#pragma unroll
            for (int mt = 0; mt < 2; mt++) {
                ldmx4(ah[mt], ldm_addr(aB,         wm * 32 + mt * 16, lane, kk * 32));
                ldmx4(al[mt], ldm_addr(aB + 16384, wm * 32 + mt * 16, lane, kk * 32));
            }
#pragma unroll
            for (int bt = 0; bt < 2; bt++) {
                uint32_t r[4];
                ldmx4(r, ldm_addr(bB, wn * 32 + bt * 16, lane, kk * 32));
                bh[bt*2][0] = r[0]; bh[bt*2][1] = r[2];
                bh[bt*2+1][0] = r[1]; bh[bt*2+1][1] = r[3];
                ldmx4(r, ldm_addr(bB + 8192, wn * 32 + bt * 16, lane, kk * 32));
                bl[bt*2][0] = r[0]; bl[bt*2][1] = r[2];
                bl[bt*2+1][0] = r[1]; bl[bt*2+1][1] = r[3];
            }
#pragma unroll
            for (int mt = 0; mt < 2; mt++)
#pragma unroll
                for (int nt = 0; nt < 4; nt++) {
                    mma16816(acc[mt][nt], ah[mt], bh[nt]);
                    mma16816(acc[mt][nt], ah[mt], bl[nt]);
                    mma16816(acc[mt][nt], al[mt], bh[nt]);
                }
        }
    };

    issueB(0, 0); loadA(0); storeA(0);
    CP_COMMIT; CP_WAIT0;
    __syncthreads();
    for (int p = 0; p < 8; p++) {
        int buf = p & 1;
        if (p < 7) { issueB(p + 1, buf ^ 1); loadA(p + 1); }
        compute(buf);
        if (p < 7) {
            storeA(buf ^ 1);
            CP_COMMIT; CP_WAIT0;
            __syncthreads();
        }
    }

    int g = lane >> 2, tig = lane & 3;
    float* hp = g_hpart + (size_t)ks * (Bsz * C * S) + (size_t)(b * 256 + mh * 128) * 64;
#pragma unroll
    for (int mt = 0; mt < 2; mt++) {
        int ca = wm * 32 + mt * 16 + g;
#pragma unroll
        for (int nt = 0; nt < 4; nt++) {
            int s0 = wn * 32 + nt * 8 + tig * 2;
            *(float2*)(hp + (size_t)ca * 64 + s0)       = make_float2(acc[mt][nt][0], acc[mt][nt][1]);
            *(float2*)(hp + (size_t)(ca + 8) * 64 + s0) = make_float2(acc[mt][nt][2], acc[mt][nt][3]);
        }
    }
}

// ---------------- h2 = w_out @ h (fp32, tiny); fused split-K reduce ----------------
__global__ __launch_bounds__(256) void h2_k(const float* __restrict__ w_out) {
    __shared__ float ws[16][65];
    __shared__ float hs[16][68];
    int m0 = blockIdx.x * 64, b = blockIdx.y;
    int tid = threadIdx.x;
    int tm = tid >> 4, tn = tid & 15;
    float acc[4][4] = {};
    int lm = tid >> 2, lk4 = (tid & 3) * 4;
    int hk = tid >> 4, hs4 = (tid & 15) * 4;
    const size_t PSTRIDE = (size_t)Bsz * C * S;
    for (int k0 = 0; k0 < C; k0 += 16) {
        float4 wv = *(const float4*)(w_out + (size_t)(m0 + lm) * C + k0 + lk4);
        size_t hoff = (size_t)(b * C + k0 + hk) * S + hs4;
        float4 hv = make_float4(0.f, 0.f, 0.f, 0.f);
#pragma unroll
        for (int p = 0; p < 8; p++) {
            float4 t = *(const float4*)(g_hpart + p * PSTRIDE + hoff);
            hv.x += t.x; hv.y += t.y; hv.z += t.z; hv.w += t.w;
        }
        __syncthreads();
        ws[lk4 + 0][lm] = wv.x; ws[lk4 + 1][lm] = wv.y;
        ws[lk4 + 2][lm] = wv.z; ws[lk4 + 3][lm] = wv.w;
        hs[hk][hs4 + 0] = hv.x; hs[hk][hs4 + 1] = hv.y;
        hs[hk][hs4 + 2] = hv.z; hs[hk][hs4 + 3] = hv.w;
        __syncthreads();
#pragma unroll
        for (int k = 0; k < 16; k++) {
            float a[4], bb[4];
#pragma unroll
            for (int i = 0; i < 4; i++) a[i] = ws[k][tm * 4 + i];
#pragma unroll
            for (int j = 0; j < 4; j++) bb[j] = hs[k][tn * 4 + j];
#pragma unroll
            for (int i = 0; i < 4; i++)
#pragma unroll
                for (int j = 0; j < 4; j++) acc[i][j] = fmaf(a[i], bb[j], acc[i][j]);
        }
    }
    float* o = g_h2 + ((size_t)b * C + m0) * S;
#pragma unroll
    for (int i = 0; i < 4; i++)
#pragma unroll
        for (int j = 0; j < 4; j++)
            o[(size_t)(tm * 4 + i) * S + tn * 4 + j] = acc[i][j];
}

// ---------------- final: out[c128][pix128] = h2 @ BC + x; K=64 ----------------
__global__ __launch_bounds__(256) void final_mma(const float* __restrict__ x,
                                                 float* __restrict__ out) {
    extern __shared__ char sm[];
    uint32_t sb = smem_u32(sm);
    const uint32_t OAH = 0, OAL = 16384, OBH = 32768, OBL = 49152;
    int tid = threadIdx.x, wid = tid >> 5, lane = tid & 31;
    int n0 = blockIdx.x * 128, mh = blockIdx.y, b = blockIdx.z;
    int wm = wid & 1, wn = wid >> 1;
    float acc[4][4][4] = {};

    float4 ar[8], br[8];
#pragma unroll
    for (int i = 0; i < 8; i++) {
        int idx = tid + i * 256;
        int row = idx >> 4, q = idx & 15;
        ar[i] = *(const float4*)(g_h2 + (size_t)(b * 256 + mh * 128 + row) * 64 + q * 4);
    }
#pragma unroll
    for (int i = 0; i < 8; i++) {
        int idx = tid + i * 256;
        int s = idx >> 5, pix4 = idx & 31;
        br[i] = *(const float4*)(g_cv + (size_t)(b * CD + s) * Nn + n0 + pix4 * 4);
    }
#pragma unroll
    for (int i = 0; i < 8; i++) {
        int idx = tid + i * 256;
        int row = idx >> 4, q = idx & 15;
        uint2 hi, lo; split_f4(ar[i], hi, lo);
        uint32_t off = SWZ((uint32_t)(row * 128 + q * 8));
        *(uint2*)(sm + OAH + off) = hi;
        *(uint2*)(sm + OAL + off) = lo;
    }
#pragma unroll
    for (int i = 0; i < 8; i++) {
        int idx = tid + i * 256;
        int s = idx >> 5, pix4 = idx & 31;
        uint2 hi, lo; split_f4(br[i], hi, lo);
        uint32_t off = (uint32_t)((pix4 >> 4) * 8192) + SWZ((uint32_t)(s * 128 + (pix4 & 15) * 8));
        *(uint2*)(sm + OBH + off) = hi;
        *(uint2*)(sm + OBL + off) = lo;
    }
    __syncthreads();

    uint32_t bB = sb + OBH + (uint32_t)((wn >> 1) * 8192);
    int pb2 = (wn & 1) * 64;
#pragma unroll
    for (int kk = 0; kk < 4; kk++) {
        uint32_t ah[4][4], al[4][4], bh[4][2], bl[4][2];
#pragma unroll
        for (int mt = 0; mt < 4; mt++) {
            ldmx4(ah[mt], ldm_addr(sb + OAH, wm * 64 + mt * 16, lane, kk * 32));
            ldmx4(al[mt], ldm_addr(sb + OAL, wm * 64 + mt * 16, lane, kk * 32));
        }
#pragma unroll
        for (int bt = 0; bt < 2; bt++) {
            uint32_t r[4];
            ldmx4t(r, ldm_addr(bB, kk * 16, lane, pb2 + bt * 32));
            bh[bt*2][0] = r[0]; bh[bt*2][1] = r[1];
            bh[bt*2+1][0] = r[2]; bh[bt*2+1][1] = r[3];
            ldmx4t(r, ldm_addr(bB + 16384, kk * 16, lane, pb2 + bt * 32));
            bl[bt*2][0] = r[0]; bl[bt*2][1] = r[1];
            bl[bt*2+1][0] = r[2]; bl[bt*2+1][1] = r[3];
        }
#pragma unroll
        for (int mt = 0; mt < 4; mt++)
#pragma unroll
            for (int nt = 0; nt < 4; nt++) {
                mma16816(acc[mt][nt], ah[mt], bh[nt]);
                mma16816(acc[mt][nt], ah[mt], bl[nt]);
                mma16816(acc[mt][nt], al[mt], bh[nt]);
            }
    }
    int g = lane >> 2, tig = lane & 3;
#pragma unroll
    for (int mt = 0; mt < 4; mt++) {
        int ca = wm * 64 + mt * 16 + g;
        size_t ra = (size_t)(b * 256 + mh * 128 + ca) * Nn + n0;
        size_t rb = ra + (size_t)8 * Nn;
#pragma unroll
        for (int nt = 0; nt < 4; nt++) {
            int px = wn * 32 + nt * 8 + tig * 2;
            float2 xa = *(const float2*)(x + ra + px);
            float2 xb = *(const float2*)(x + rb + px);
            *(float2*)(out + ra + px) = make_float2(acc[mt][nt][0] + xa.x, acc[mt][nt][1] + xa.y);
            *(float2*)(out + rb + px) = make_float2(acc[mt][nt][2] + xb.x, acc[mt][nt][3] + xb.y);
        }
    }
}

// ---------------- launcher ----------------
extern "C" void kernel_launch(void* const* d_in, const int* in_sizes, int n_in,
                              void* d_out, int out_size) {
    const float* x      = (const float*)d_in[0];
    const float* ln_w   = (const float*)d_in[1];
    const float* ln_b   = (const float*)d_in[2];
    const float* w_bcdt = (const float*)d_in[3];
    const float* w_gw   = (const float*)d_in[4];
    const float* w_out  = (const float*)d_in[5];
    const float* A      = (const float*)d_in[6];
    float* out = (float*)d_out;

    cudaFuncSetAttribute(gemm1_mma, cudaFuncAttributeMaxDynamicSharedMemorySize, 131072);
    cudaFuncSetAttribute(hgemm_mma, cudaFuncAttributeMaxDynamicSharedMemorySize, 98304);
    cudaFuncSetAttribute(final_mma, cudaFuncAttributeMaxDynamicSharedMemorySize, 65536);

    prep_w_k<<<128, 256>>>(w_bcdt, ln_w, ln_b);
    gemm1_mma<<<dim3(32, Bsz), 256, 131072>>>(x);
    conv_k<<<dim3(2, 32, Bsz), 256>>>(w_gw);
    softmax_k<<<dim3(S, Bsz), 256>>>(A);
    hgemm_mma<<<dim3(8, 2, Bsz), 256, 98304>>>(x);
    h2_k<<<dim3(C / 64, Bsz), 256>>>(w_out);
    final_mma<<<dim3(32, 2, Bsz), 256, 65536>>>(x, out);
}